// round 1
// baseline (speedup 1.0000x reference)
#include <cuda_runtime.h>
#include <math.h>

#define B 32
#define C 512
#define Q 128
#define D 768
#define NEG (-1e30f)
#define BK 16

// ---------------- scratch (static device allocs are the sanctioned path) ----
__device__ float g_sim[(size_t)B * C * Q];   // 8.4 MB similarity
__device__ float g_cw1[B * C];
__device__ float g_qw2[B * Q];
__device__ float g_Smax[B * C];
__device__ float g_pmax[B * 8 * Q];
__device__ float g_psum[B * 8 * Q];
__device__ float g_colmax[B * Q];
__device__ float g_colinv[B * Q];
__device__ float g_cdist[B * C];
__device__ float g_cdash[B * D];

// ---------------- K0: cw1[b,c] = C·w1 ; qw2[b,q] = Q·w2 ----------------------
__global__ void k_rowdots(const float* __restrict__ cont,
                          const float* __restrict__ ques,
                          const float* __restrict__ SW) {
    int row = blockIdx.x;
    const float* x; const float* w; float* o;
    if (row < B * C) {
        x = cont + (size_t)row * D; w = SW;     o = g_cw1 + row;
    } else {
        int r = row - B * C;
        x = ques + (size_t)r * D;   w = SW + D; o = g_qw2 + r;
    }
    int t = threadIdx.x;
    float s = 0.f;
    for (int d = t; d < D; d += 256) s += x[d] * w[d];
    __shared__ float red[8];
    #pragma unroll
    for (int off = 16; off; off >>= 1) s += __shfl_xor_sync(~0u, s, off);
    if ((t & 31) == 0) red[t >> 5] = s;
    __syncthreads();
    if (t < 8) {
        s = red[t];
        #pragma unroll
        for (int off = 4; off; off >>= 1) s += __shfl_xor_sync(0xffu, s, off);
        if (t == 0) *o = s;
    }
}

// ---------------- K1: sim[b,c,q] = (c*w3)·q + cw1 + qw2 ----------------------
// Per batch NT GEMM: M=512(c), N=128(q), K=768. 128x128 block tile, 8x8/thread.
__global__ __launch_bounds__(256) void k_sim(const float* __restrict__ cont,
                                             const float* __restrict__ ques,
                                             const float* __restrict__ SW) {
    int b  = blockIdx.z;
    int cm = blockIdx.x * 128;
    __shared__ float As[BK][132];
    __shared__ float Bs[BK][132];
    const float* A  = cont + ((size_t)b * C + cm) * D;
    const float* Bq = ques + (size_t)b * Q * D;
    const float* w3 = SW + 2 * D;
    int t  = threadIdx.x;
    int ty = t >> 4, tx = t & 15;
    int lrow = t >> 2;
    int lc4  = (t & 3) << 2;
    float acc[8][8] = {};
    for (int k0 = 0; k0 < D; k0 += BK) {
        #pragma unroll
        for (int r = 0; r < 2; r++) {
            int row = lrow + r * 64;
            float4 av = *(const float4*)&A[(size_t)row * D + k0 + lc4];
            float4 wv = *(const float4*)&w3[k0 + lc4];
            As[lc4 + 0][row] = av.x * wv.x;
            As[lc4 + 1][row] = av.y * wv.y;
            As[lc4 + 2][row] = av.z * wv.z;
            As[lc4 + 3][row] = av.w * wv.w;
            float4 bv = *(const float4*)&Bq[(size_t)row * D + k0 + lc4];
            Bs[lc4 + 0][row] = bv.x;
            Bs[lc4 + 1][row] = bv.y;
            Bs[lc4 + 2][row] = bv.z;
            Bs[lc4 + 3][row] = bv.w;
        }
        __syncthreads();
        #pragma unroll
        for (int kk = 0; kk < BK; kk++) {
            float a[8], bb[8];
            #pragma unroll
            for (int i = 0; i < 8; i++) a[i]  = As[kk][ty * 8 + i];
            #pragma unroll
            for (int j = 0; j < 8; j++) bb[j] = Bs[kk][tx * 8 + j];
            #pragma unroll
            for (int i = 0; i < 8; i++)
                #pragma unroll
                for (int j = 0; j < 8; j++)
                    acc[i][j] = fmaf(a[i], bb[j], acc[i][j]);
        }
        __syncthreads();
    }
    #pragma unroll
    for (int i = 0; i < 8; i++) {
        int cc = cm + ty * 8 + i;
        float cw = g_cw1[b * C + cc];
        float* orow = g_sim + ((size_t)b * C + cc) * Q;
        #pragma unroll
        for (int j = 0; j < 8; j++) {
            int qq = tx * 8 + j;
            orow[qq] = acc[i][j] + cw + g_qw2[b * Q + qq];
        }
    }
}

// ---------------- K2a: S_max[b,c] = max_q sim (unmasked) ---------------------
__global__ void k_smax() {
    int gw   = (blockIdx.x * 256 + threadIdx.x) >> 5;   // one warp per row
    int lane = threadIdx.x & 31;
    const float* row = g_sim + (size_t)gw * Q;
    float m = row[lane];
    m = fmaxf(m, row[lane + 32]);
    m = fmaxf(m, row[lane + 64]);
    m = fmaxf(m, row[lane + 96]);
    #pragma unroll
    for (int off = 16; off; off >>= 1)
        m = fmaxf(m, __shfl_xor_sync(~0u, m, off));
    if (!lane) g_Smax[gw] = m;
}

// ---------------- K2b: column softmax stats (partial, 64 c per block) --------
__global__ void k_colpart(const int* __restrict__ qmask) {
    int b = blockIdx.x, ch = blockIdx.y;
    int q = threadIdx.x;                                   // 128 threads
    float addend = (1.0f - (float)qmask[b * Q + q]) * NEG;
    const float* base = g_sim + ((size_t)b * C + ch * 64) * Q + q;
    float m = -INFINITY;
    #pragma unroll 8
    for (int c = 0; c < 64; c++) m = fmaxf(m, base[(size_t)c * Q] + addend);
    float s = 0.f;
    #pragma unroll 8
    for (int c = 0; c < 64; c++) s += expf((base[(size_t)c * Q] + addend) - m);
    g_pmax[(b * 8 + ch) * Q + q] = m;
    g_psum[(b * 8 + ch) * Q + q] = s;
}

// ---------------- K2c: merge partials (online softmax combine) ---------------
__global__ void k_colfin() {
    int b = blockIdx.x, q = threadIdx.x;
    float pm[8], ps[8];
    float m = -INFINITY;
    #pragma unroll
    for (int ch = 0; ch < 8; ch++) {
        pm[ch] = g_pmax[(b * 8 + ch) * Q + q];
        ps[ch] = g_psum[(b * 8 + ch) * Q + q];
        m = fmaxf(m, pm[ch]);
    }
    float s = 0.f;
    #pragma unroll
    for (int ch = 0; ch < 8; ch++) s += ps[ch] * expf(pm[ch] - m);
    g_colmax[b * Q + q] = m;
    g_colinv[b * Q + q] = 1.0f / s;
}

// ---------------- K3a: c_dash_dist = softmax_c(S_max + cmask) ----------------
__global__ void k_cdist(const int* __restrict__ cmask) {     // 32 blocks, 256 thr
    int b = blockIdx.x, t = threadIdx.x;
    __shared__ float red[256];
    float v0 = g_Smax[b * C + t]       + (1.0f - (float)cmask[b * C + t]) * NEG;
    float v1 = g_Smax[b * C + 256 + t] + (1.0f - (float)cmask[b * C + 256 + t]) * NEG;
    red[t] = fmaxf(v0, v1);
    __syncthreads();
    for (int s = 128; s; s >>= 1) {
        if (t < s) red[t] = fmaxf(red[t], red[t + s]);
        __syncthreads();
    }
    float m = red[0];
    __syncthreads();
    float e0 = expf(v0 - m), e1 = expf(v1 - m);
    red[t] = e0 + e1;
    __syncthreads();
    for (int s = 128; s; s >>= 1) {
        if (t < s) red[t] += red[t + s];
        __syncthreads();
    }
    float inv = 1.0f / red[0];
    g_cdist[b * C + t]       = e0 * inv;
    g_cdist[b * C + 256 + t] = e1 * inv;
}

// ---------------- K3b: c_dash[b,d] = sum_c dist[c] * C[b,c,d] ----------------
__global__ void k_cdash(const float* __restrict__ cont) {    // grid (B,6), 128 thr
    int b = blockIdx.x;
    int d = blockIdx.y * 128 + threadIdx.x;
    const float* cb   = cont + (size_t)b * C * D + d;
    const float* dist = g_cdist + b * C;
    float acc = 0.f;
    #pragma unroll 4
    for (int c = 0; c < C; c++) acc = fmaf(dist[c], cb[(size_t)c * D], acc);
    g_cdash[b * D + d] = acc;
}

// ---------------- K4: c2q = P @ Q  +  fused 4-chunk epilogue -----------------
// Per batch NN GEMM: M=512(c), N=768(d), K=128(q). A built on-the-fly from sim.
__global__ __launch_bounds__(256) void k_c2q(const float* __restrict__ cont,
                                             const float* __restrict__ ques,
                                             const int*   __restrict__ qmask,
                                             float* __restrict__ out) {
    int b  = blockIdx.z;
    int cm = blockIdx.x * 128;
    int dn = blockIdx.y * 128;
    __shared__ float As[BK][132];
    __shared__ float Bs[BK][132];
    __shared__ float s_add[Q], s_max[Q], s_inv[Q];
    int t = threadIdx.x;
    if (t < Q) {
        s_add[t] = (1.0f - (float)qmask[b * Q + t]) * NEG;
        s_max[t] = g_colmax[b * Q + t];
        s_inv[t] = g_colinv[b * Q + t];
    }
    __syncthreads();
    int ty = t >> 4, tx = t & 15;
    float acc[8][8] = {};
    const float* simb = g_sim + ((size_t)b * C + cm) * Q;
    const float* Bq   = ques + (size_t)b * Q * D + dn;

    for (int k0 = 0; k0 < Q; k0 += BK) {
        {   // A tile: 128 c-rows x 16 q, transformed to P on the fly
            int row = t >> 2;
            int c4  = (t & 3) << 2;
            #pragma unroll
            for (int r = 0; r < 2; r++) {
                int rr = row + r * 64;
                float4 sv = *(const float4*)&simb[(size_t)rr * Q + k0 + c4];
                float v[4] = {sv.x, sv.y, sv.z, sv.w};
                #pragma unroll
                for (int j = 0; j < 4; j++) {
                    int q = k0 + c4 + j;
                    As[c4 + j][rr] = expf((v[j] + s_add[q]) - s_max[q]) * s_inv[q];
                }
            }
        }
        {   // B tile: 16 q-rows x 128 d
            #pragma unroll
            for (int r = 0; r < 2; r++) {
                int idx  = t + r * 256;
                int row  = idx >> 5;
                int dcol = (idx & 31) << 2;
                float4 bv = *(const float4*)&Bq[(size_t)(k0 + row) * D + dcol];
                *(float4*)&Bs[row][dcol] = bv;
            }
        }
        __syncthreads();
        #pragma unroll
        for (int kk = 0; kk < BK; kk++) {
            float a[8], bb[8];
            #pragma unroll
            for (int i = 0; i < 8; i++) a[i]  = As[kk][ty * 8 + i];
            #pragma unroll
            for (int j = 0; j < 8; j++) bb[j] = Bs[kk][tx * 8 + j];
            #pragma unroll
            for (int i = 0; i < 8; i++)
                #pragma unroll
                for (int j = 0; j < 8; j++)
                    acc[i][j] = fmaf(a[i], bb[j], acc[i][j]);
        }
        __syncthreads();
    }

    // epilogue: out = [ c | c2q | c*c2q | c*c_dash ]
    float cd[8];
    #pragma unroll
    for (int j = 0; j < 8; j++) cd[j] = g_cdash[b * D + dn + tx * 8 + j];
    #pragma unroll
    for (int i = 0; i < 8; i++) {
        int cc = cm + ty * 8 + i;
        const float* crow = cont + ((size_t)b * C + cc) * D + dn + tx * 8;
        float* obase = out + ((size_t)b * C + cc) * (4 * D);
        int d = dn + tx * 8;
        #pragma unroll
        for (int j = 0; j < 8; j += 4) {
            float4 cv = *(const float4*)&crow[j];
            float4 v  = make_float4(acc[i][j], acc[i][j + 1], acc[i][j + 2], acc[i][j + 3]);
            *(float4*)&obase[d + j]         = cv;
            *(float4*)&obase[D + d + j]     = v;
            *(float4*)&obase[2 * D + d + j] = make_float4(cv.x * v.x, cv.y * v.y,
                                                          cv.z * v.z, cv.w * v.w);
            *(float4*)&obase[3 * D + d + j] = make_float4(cv.x * cd[j],     cv.y * cd[j + 1],
                                                          cv.z * cd[j + 2], cv.w * cd[j + 3]);
        }
    }
}

// ---------------- launch -----------------------------------------------------
extern "C" void kernel_launch(void* const* d_in, const int* in_sizes, int n_in,
                              void* d_out, int out_size) {
    const float* cont  = (const float*)d_in[0];
    const int*   cmask = (const int*)d_in[1];
    const float* ques  = (const float*)d_in[2];
    const int*   qmask = (const int*)d_in[3];
    const float* SW    = (const float*)d_in[4];
    float* out = (float*)d_out;

    k_rowdots<<<B * C + B * Q, 256>>>(cont, ques, SW);
    k_sim<<<dim3(C / 128, 1, B), 256>>>(cont, ques, SW);
    k_smax<<<(B * C * 32) / 256, 256>>>();
    k_colpart<<<dim3(B, 8), Q>>>(qmask);
    k_colfin<<<B, Q>>>();
    k_cdist<<<B, 256>>>(cmask);
    k_cdash<<<dim3(B, 6), 128>>>(cont);
    k_c2q<<<dim3(C / 128, D / 128, B), 256>>>(cont, ques, qmask, out);
}

// round 2
// speedup vs baseline: 1.3287x; 1.3287x over previous
#include <cuda_runtime.h>
#include <math.h>

#define B 32
#define C 512
#define Q 128
#define D 768
#define NEG (-1e30f)
#define NCH 16   // column-softmax partial chunks

// ---------------- scratch ----------------------------------------------------
__device__ float g_sim[(size_t)B * C * Q];
__device__ float g_cw1[B * C];
__device__ float g_qw2[B * Q];
__device__ float g_Smax[B * C];
__device__ float g_pmax[B * NCH * Q];
__device__ float g_psum[B * NCH * Q];
__device__ float g_colmax[B * Q];
__device__ float g_colinv[B * Q];
__device__ float g_cdist[B * C];
__device__ float g_cdash[B * D];

// ---------------- tf32 helpers ----------------------------------------------
__device__ __forceinline__ unsigned f2tf(float f) {
    unsigned u; asm("cvt.rna.tf32.f32 %0, %1;" : "=r"(u) : "f"(f)); return u;
}
__device__ __forceinline__ void mma_tf32(float* d, const unsigned* a, const unsigned* b) {
    asm volatile("mma.sync.aligned.m16n8k8.row.col.f32.tf32.tf32.f32 "
                 "{%0,%1,%2,%3}, {%4,%5,%6,%7}, {%8,%9}, {%0,%1,%2,%3};"
                 : "+f"(d[0]), "+f"(d[1]), "+f"(d[2]), "+f"(d[3])
                 : "r"(a[0]), "r"(a[1]), "r"(a[2]), "r"(a[3]), "r"(b[0]), "r"(b[1]));
}

// ---------------- K0: cw1[b,c] = C·w1 ; qw2[b,q] = Q·w2 ----------------------
__global__ void k_rowdots(const float* __restrict__ cont,
                          const float* __restrict__ ques,
                          const float* __restrict__ SW) {
    int row = blockIdx.x;
    const float* x; const float* w; float* o;
    if (row < B * C) { x = cont + (size_t)row * D; w = SW;     o = g_cw1 + row; }
    else { int r = row - B * C; x = ques + (size_t)r * D; w = SW + D; o = g_qw2 + r; }
    int t = threadIdx.x;
    float s = 0.f;
    for (int d = t; d < D; d += 256) s += x[d] * w[d];
    __shared__ float red[8];
    #pragma unroll
    for (int off = 16; off; off >>= 1) s += __shfl_xor_sync(~0u, s, off);
    if ((t & 31) == 0) red[t >> 5] = s;
    __syncthreads();
    if (t < 8) {
        s = red[t];
        #pragma unroll
        for (int off = 4; off; off >>= 1) s += __shfl_xor_sync(0xffu, s, off);
        if (t == 0) *o = s;
    }
}

// ---------------- K1: sim = (c*w3)·qT + cw1 + qw2, fused S_max ---------------
// tf32 tensor-core GEMM. M=512(c) split in 4 blocks, N=128(q), K=768.
// smem: As[2][128][36], Bs[2][128][36] tf32, red[2][128] f32
__global__ __launch_bounds__(256) void k_sim_mma(const float* __restrict__ cont,
                                                 const float* __restrict__ ques,
                                                 const float* __restrict__ SW) {
    const int b  = blockIdx.z;
    const int cm = blockIdx.x * 128;
    extern __shared__ unsigned smemu[];
    unsigned* As = smemu;                 // [2][128][36]
    unsigned* Bs = smemu + 2 * 128 * 36;  // [2][128][36]
    float*   red = (float*)(smemu + 4 * 128 * 36);  // [2][128]

    const int t = threadIdx.x, lane = t & 31, warp = t >> 5;
    const int g = lane >> 2, tg = lane & 3;
    const int wm = (warp & 3) * 32;
    const int wn = (warp >> 2) * 64;

    const float* w3 = SW + 2 * D;
    const int lr = t >> 1;
    const int lk = (t & 1) * 16;
    const float* Ag = cont + ((size_t)(b * C + cm + lr)) * D + lk;
    const float* Bg = ques + ((size_t)(b * Q + lr)) * D + lk;

    float acc[2][8][4];
    #pragma unroll
    for (int i = 0; i < 2; i++)
        #pragma unroll
        for (int j = 0; j < 8; j++)
            #pragma unroll
            for (int k = 0; k < 4; k++) acc[i][j][k] = 0.f;

    float4 pa[4], pb[4];
    #pragma unroll
    for (int j = 0; j < 4; j++) {
        pa[j] = *(const float4*)(Ag + j * 4);
        pb[j] = *(const float4*)(Bg + j * 4);
    }

    const int NST = D / 32;   // 24
    for (int s = 0; s < NST; s++) {
        const int buf = s & 1;
        {   // STS (w3 multiply + tf32 round)
            unsigned* a  = As + buf * 128 * 36 + lr * 36 + lk;
            unsigned* bp = Bs + buf * 128 * 36 + lr * 36 + lk;
            #pragma unroll
            for (int j = 0; j < 4; j++) {
                float4 wv = *(const float4*)(w3 + s * 32 + lk + j * 4);
                uint4 av, bv;
                av.x = f2tf(pa[j].x * wv.x); av.y = f2tf(pa[j].y * wv.y);
                av.z = f2tf(pa[j].z * wv.z); av.w = f2tf(pa[j].w * wv.w);
                bv.x = f2tf(pb[j].x); bv.y = f2tf(pb[j].y);
                bv.z = f2tf(pb[j].z); bv.w = f2tf(pb[j].w);
                *(uint4*)(a  + j * 4) = av;
                *(uint4*)(bp + j * 4) = bv;
            }
        }
        __syncthreads();
        if (s + 1 < NST) {
            #pragma unroll
            for (int j = 0; j < 4; j++) {
                pa[j] = *(const float4*)(Ag + (s + 1) * 32 + j * 4);
                pb[j] = *(const float4*)(Bg + (s + 1) * 32 + j * 4);
            }
        }
        const unsigned* ab = As + buf * 128 * 36;
        const unsigned* bb = Bs + buf * 128 * 36;
        #pragma unroll
        for (int k8 = 0; k8 < 32; k8 += 8) {
            unsigned afr[2][4];
            #pragma unroll
            for (int mi = 0; mi < 2; mi++) {
                int r0 = wm + mi * 16 + g;
                afr[mi][0] = ab[r0 * 36 + k8 + tg];
                afr[mi][1] = ab[(r0 + 8) * 36 + k8 + tg];
                afr[mi][2] = ab[r0 * 36 + k8 + tg + 4];
                afr[mi][3] = ab[(r0 + 8) * 36 + k8 + tg + 4];
            }
            #pragma unroll
            for (int ni = 0; ni < 8; ni++) {
                int nb = wn + ni * 8 + g;
                unsigned bfr[2];
                bfr[0] = bb[nb * 36 + k8 + tg];
                bfr[1] = bb[nb * 36 + k8 + tg + 4];
                mma_tf32(acc[0][ni], afr[0], bfr);
                mma_tf32(acc[1][ni], afr[1], bfr);
            }
        }
    }

    // epilogue: +cw1 +qw2, store sim, fused row-max -> g_Smax
    float qv0[8], qv1[8];
    #pragma unroll
    for (int ni = 0; ni < 8; ni++) {
        int col = wn + ni * 8 + 2 * tg;
        float2 qq = *(const float2*)&g_qw2[b * Q + col];
        qv0[ni] = qq.x; qv1[ni] = qq.y;
    }
    #pragma unroll
    for (int mi = 0; mi < 2; mi++) {
        #pragma unroll
        for (int half = 0; half < 2; half++) {
            int rloc = wm + mi * 16 + g + half * 8;
            int row  = cm + rloc;
            float cw = g_cw1[b * C + row];
            float* orow = g_sim + ((size_t)b * C + row) * Q + wn;
            float m = -INFINITY;
            #pragma unroll
            for (int ni = 0; ni < 8; ni++) {
                float v0 = acc[mi][ni][half * 2 + 0] + cw + qv0[ni];
                float v1 = acc[mi][ni][half * 2 + 1] + cw + qv1[ni];
                *(float2*)(orow + ni * 8 + 2 * tg) = make_float2(v0, v1);
                m = fmaxf(m, fmaxf(v0, v1));
            }
            m = fmaxf(m, __shfl_xor_sync(~0u, m, 1));
            m = fmaxf(m, __shfl_xor_sync(~0u, m, 2));
            if (tg == 0) red[(warp >> 2) * 128 + rloc] = m;
        }
    }
    __syncthreads();
    if (t < 128) g_Smax[b * C + cm + t] = fmaxf(red[t], red[128 + t]);
}

// ---------------- K2b: column softmax partials -------------------------------
__global__ void k_colpart(const int* __restrict__ qmask) {
    int b = blockIdx.x, ch = blockIdx.y;
    int q = threadIdx.x;
    float addend = (1.0f - (float)qmask[b * Q + q]) * NEG;
    const float* base = g_sim + ((size_t)b * C + ch * (C / NCH)) * Q + q;
    float m = -INFINITY;
    #pragma unroll 8
    for (int c = 0; c < C / NCH; c++) m = fmaxf(m, base[(size_t)c * Q] + addend);
    float s = 0.f;
    #pragma unroll 8
    for (int c = 0; c < C / NCH; c++) s += expf((base[(size_t)c * Q] + addend) - m);
    g_pmax[(b * NCH + ch) * Q + q] = m;
    g_psum[(b * NCH + ch) * Q + q] = s;
}

// ---------------- K2c: merge partials ----------------------------------------
__global__ void k_colfin() {
    int b = blockIdx.x, q = threadIdx.x;
    float pm[NCH], ps[NCH];
    float m = -INFINITY;
    #pragma unroll
    for (int ch = 0; ch < NCH; ch++) {
        pm[ch] = g_pmax[(b * NCH + ch) * Q + q];
        ps[ch] = g_psum[(b * NCH + ch) * Q + q];
        m = fmaxf(m, pm[ch]);
    }
    float s = 0.f;
    #pragma unroll
    for (int ch = 0; ch < NCH; ch++) s += ps[ch] * expf(pm[ch] - m);
    g_colmax[b * Q + q] = m;
    g_colinv[b * Q + q] = 1.0f / s;
}

// ---------------- K3a: c_dash_dist = softmax_c(S_max + cmask) ----------------
__global__ void k_cdist(const int* __restrict__ cmask) {
    int b = blockIdx.x, t = threadIdx.x;
    __shared__ float red[256];
    float v0 = g_Smax[b * C + t]       + (1.0f - (float)cmask[b * C + t]) * NEG;
    float v1 = g_Smax[b * C + 256 + t] + (1.0f - (float)cmask[b * C + 256 + t]) * NEG;
    red[t] = fmaxf(v0, v1);
    __syncthreads();
    for (int s = 128; s; s >>= 1) {
        if (t < s) red[t] = fmaxf(red[t], red[t + s]);
        __syncthreads();
    }
    float m = red[0];
    __syncthreads();
    float e0 = expf(v0 - m), e1 = expf(v1 - m);
    red[t] = e0 + e1;
    __syncthreads();
    for (int s = 128; s; s >>= 1) {
        if (t < s) red[t] += red[t + s];
        __syncthreads();
    }
    float inv = 1.0f / red[0];
    g_cdist[b * C + t]       = e0 * inv;
    g_cdist[b * C + 256 + t] = e1 * inv;
}

// ---------------- K3b: c_dash[b,d] = sum_c dist[c] * C[b,c,d] ----------------
__global__ void k_cdash(const float* __restrict__ cont) {
    int b = blockIdx.x;
    int d = blockIdx.y * 128 + threadIdx.x;
    const float* cb   = cont + (size_t)b * C * D + d;
    const float* dist = g_cdist + b * C;
    float acc = 0.f;
    #pragma unroll 4
    for (int c = 0; c < C; c++) acc = fmaf(dist[c], cb[(size_t)c * D], acc);
    g_cdash[b * D + d] = acc;
}

// ---------------- K4: c2q = P @ Q with on-the-fly P, fused epilogue ----------
// tf32 GEMM: M=512(c), N=768(d), K=128(q). A = exp((sim+add)-max)*inv.
// smem: As[2][128][36], Bs[2][32][132] tf32, + 3*128 f32
__global__ __launch_bounds__(256) void k_c2q_mma(const float* __restrict__ cont,
                                                 const float* __restrict__ ques,
                                                 const int*   __restrict__ qmask,
                                                 float* __restrict__ out) {
    const int b  = blockIdx.z;
    const int cm = blockIdx.x * 128;
    const int dn = blockIdx.y * 128;
    extern __shared__ unsigned smemu[];
    unsigned* As = smemu;                 // [2][128][36]
    unsigned* Bs = smemu + 2 * 128 * 36;  // [2][32][132]
    float* s_add = (float*)(Bs + 2 * 32 * 132);
    float* s_max = s_add + 128;
    float* s_inv = s_max + 128;

    const int t = threadIdx.x, lane = t & 31, warp = t >> 5;
    const int g = lane >> 2, tg = lane & 3;
    const int wm = (warp & 3) * 32;
    const int wn = (warp >> 2) * 64;

    if (t < Q) {
        s_add[t] = (1.0f - (float)qmask[b * Q + t]) * NEG;
        s_max[t] = g_colmax[b * Q + t];
        s_inv[t] = g_colinv[b * Q + t];
    }
    __syncthreads();

    const int lr = t >> 1;
    const int lk = (t & 1) * 16;
    const float* Ag = g_sim + ((size_t)(b * C + cm + lr)) * Q + lk;
    const int br = t >> 3;
    const int bd = (t & 7) * 4;
    const float* quesb = ques + (size_t)b * Q * D + dn + bd;

    float acc[2][8][4];
    #pragma unroll
    for (int i = 0; i < 2; i++)
        #pragma unroll
        for (int j = 0; j < 8; j++)
            #pragma unroll
            for (int k = 0; k < 4; k++) acc[i][j][k] = 0.f;

    float4 pa[4], pb[4];
    #pragma unroll
    for (int j = 0; j < 4; j++) {
        pa[j] = *(const float4*)(Ag + j * 4);
        pb[j] = *(const float4*)(quesb + (size_t)br * D + j * 32);
    }

    const int NST = Q / 32;   // 4
    #pragma unroll 1
    for (int s = 0; s < NST; s++) {
        const int buf = s & 1;
        {
            unsigned* a  = As + buf * 128 * 36 + lr * 36 + lk;
            unsigned* bp = Bs + buf * 32 * 132 + br * 132 + bd;
            #pragma unroll
            for (int j = 0; j < 4; j++) {
                int qb = s * 32 + lk + j * 4;
                uint4 av, bv;
                av.x = f2tf(expf((pa[j].x + s_add[qb+0]) - s_max[qb+0]) * s_inv[qb+0]);
                av.y = f2tf(expf((pa[j].y + s_add[qb+1]) - s_max[qb+1]) * s_inv[qb+1]);
                av.z = f2tf(expf((pa[j].z + s_add[qb+2]) - s_max[qb+2]) * s_inv[qb+2]);
                av.w = f2tf(expf((pa[j].w + s_add[qb+3]) - s_max[qb+3]) * s_inv[qb+3]);
                bv.x = f2tf(pb[j].x); bv.y = f2tf(pb[j].y);
                bv.z = f2tf(pb[j].z); bv.w = f2tf(pb[j].w);
                *(uint4*)(a  + j * 4)  = av;
                *(uint4*)(bp + j * 32) = bv;
            }
        }
        __syncthreads();
        if (s + 1 < NST) {
            #pragma unroll
            for (int j = 0; j < 4; j++) {
                pa[j] = *(const float4*)(Ag + (s + 1) * 32 + j * 4);
                pb[j] = *(const float4*)(quesb + (size_t)((s + 1) * 32 + br) * D + j * 32);
            }
        }
        const unsigned* ab = As + buf * 128 * 36;
        const unsigned* bb = Bs + buf * 32 * 132;
        #pragma unroll
        for (int k8 = 0; k8 < 32; k8 += 8) {
            unsigned afr[2][4];
            #pragma unroll
            for (int mi = 0; mi < 2; mi++) {
                int r0 = wm + mi * 16 + g;
                afr[mi][0] = ab[r0 * 36 + k8 + tg];
                afr[mi][1] = ab[(r0 + 8) * 36 + k8 + tg];
                afr[mi][2] = ab[r0 * 36 + k8 + tg + 4];
                afr[mi][3] = ab[(r0 + 8) * 36 + k8 + tg + 4];
            }
            #pragma unroll
            for (int ni = 0; ni < 8; ni++) {
                int nb = wn + ni * 8 + g;
                unsigned bfr[2];
                bfr[0] = bb[(k8 + tg) * 132 + nb];
                bfr[1] = bb[(k8 + tg + 4) * 132 + nb];
                mma_tf32(acc[0][ni], afr[0], bfr);
                mma_tf32(acc[1][ni], afr[1], bfr);
            }
        }
    }

    // epilogue: out = [ c | c2q | c*c2q | c*c_dash ]
    #pragma unroll
    for (int mi = 0; mi < 2; mi++) {
        #pragma unroll
        for (int half = 0; half < 2; half++) {
            int cc = cm + wm + mi * 16 + g + half * 8;
            const float* crow = cont + ((size_t)b * C + cc) * D + dn;
            float* obase = out + ((size_t)b * C + cc) * (4 * D);
            #pragma unroll
            for (int ni = 0; ni < 8; ni++) {
                int col = wn + ni * 8 + 2 * tg;
                int dg  = dn + col;
                float2 cv = *(const float2*)(crow + col);
                float2 cd = *(const float2*)&g_cdash[b * D + dg];
                float2 v  = make_float2(acc[mi][ni][half * 2 + 0],
                                        acc[mi][ni][half * 2 + 1]);
                *(float2*)&obase[dg]           = cv;
                *(float2*)&obase[D + dg]       = v;
                *(float2*)&obase[2 * D + dg]   = make_float2(cv.x * v.x, cv.y * v.y);
                *(float2*)&obase[3 * D + dg]   = make_float2(cv.x * cd.x, cv.y * cd.y);
            }
        }
    }
}

// ---------------- launch -----------------------------------------------------
extern "C" void kernel_launch(void* const* d_in, const int* in_sizes, int n_in,
                              void* d_out, int out_size) {
    const float* cont  = (const float*)d_in[0];
    const int*   cmask = (const int*)d_in[1];
    const float* ques  = (const float*)d_in[2];
    const int*   qmask = (const int*)d_in[3];
    const float* SW    = (const float*)d_in[4];
    float* out = (float*)d_out;

    const int smem_sim = (4 * 128 * 36) * 4 + 2 * 128 * 4;          // 74752 B
    const int smem_c2q = (2 * 128 * 36 + 2 * 32 * 132) * 4 + 3 * 128 * 4;  // 72192 B
    cudaFuncSetAttribute(k_sim_mma, cudaFuncAttributeMaxDynamicSharedMemorySize, smem_sim);
    cudaFuncSetAttribute(k_c2q_mma, cudaFuncAttributeMaxDynamicSharedMemorySize, smem_c2q);

    k_rowdots<<<B * C + B * Q, 256>>>(cont, ques, SW);
    k_sim_mma<<<dim3(C / 128, 1, B), 256, smem_sim>>>(cont, ques, SW);
    k_colpart<<<dim3(B, NCH), Q>>>(qmask);
    k_colfin<<<B, Q>>>();
    k_cdist<<<B, 256>>>(cmask);
    k_cdash<<<dim3(B, 6), 128>>>(cont);
    k_c2q_mma<<<dim3(C / 128, D / 128, B), 256, smem_c2q>>>(cont, ques, qmask, out);
}

// round 3
// speedup vs baseline: 1.4219x; 1.0701x over previous
#include <cuda_runtime.h>
#include <math.h>

#define B 32
#define C 512
#define Q 128
#define D 768
#define NEG (-1e30f)
#define NCH 16

// ---------------- scratch ----------------------------------------------------
__device__ float g_sim[(size_t)B * C * Q];
__device__ float g_Smax[B * C];
__device__ float g_pmax[B * NCH * Q];
__device__ float g_psum[B * NCH * Q];
__device__ float g_colmax[B * Q];
__device__ float g_colinv[B * Q];
__device__ float g_cdist[B * C];
__device__ float g_cdash[B * D];

// ---------------- tf32 helpers ----------------------------------------------
__device__ __forceinline__ unsigned f2tf(float f) {
    unsigned u; asm("cvt.rna.tf32.f32 %0, %1;" : "=r"(u) : "f"(f)); return u;
}
__device__ __forceinline__ void mma_tf32(float* d, const unsigned* a, const unsigned* b) {
    asm volatile("mma.sync.aligned.m16n8k8.row.col.f32.tf32.tf32.f32 "
                 "{%0,%1,%2,%3}, {%4,%5,%6,%7}, {%8,%9}, {%0,%1,%2,%3};"
                 : "+f"(d[0]), "+f"(d[1]), "+f"(d[2]), "+f"(d[3])
                 : "r"(a[0]), "r"(a[1]), "r"(a[2]), "r"(a[3]), "r"(b[0]), "r"(b[1]));
}

// ---------------- K1: sim = (c*w3)·qT + cw1 + qw2 (dots fused), S_max --------
// smem: As[2][128][36], Bs[2][128][36] tf32, red[256], s_cw[128], s_qw[128]
__global__ __launch_bounds__(256) void k_sim_mma(const float* __restrict__ cont,
                                                 const float* __restrict__ ques,
                                                 const float* __restrict__ SW) {
    const int b  = blockIdx.z;
    const int cm = blockIdx.x * 128;
    extern __shared__ unsigned smemu[];
    unsigned* As = smemu;
    unsigned* Bs = smemu + 2 * 128 * 36;
    float*   red = (float*)(smemu + 4 * 128 * 36);
    float*  s_cw = red + 256;
    float*  s_qw = s_cw + 128;

    const int t = threadIdx.x, lane = t & 31, warp = t >> 5;
    const int g = lane >> 2, tg = lane & 3;
    const int wm = (warp & 3) * 32;
    const int wn = (warp >> 2) * 64;

    const float* w1 = SW;
    const float* w2 = SW + D;
    const float* w3 = SW + 2 * D;
    const int lr = t >> 1;
    const int lk = (t & 1) * 16;
    const float* Ag = cont + ((size_t)(b * C + cm + lr)) * D + lk;
    const float* Bg = ques + ((size_t)(b * Q + lr)) * D + lk;

    float acc[2][8][4];
    #pragma unroll
    for (int i = 0; i < 2; i++)
        #pragma unroll
        for (int j = 0; j < 8; j++)
            #pragma unroll
            for (int k = 0; k < 4; k++) acc[i][j][k] = 0.f;

    float cwacc = 0.f, qwacc = 0.f;

    float4 pa[4], pb[4];
    #pragma unroll
    for (int j = 0; j < 4; j++) {
        pa[j] = *(const float4*)(Ag + j * 4);
        pb[j] = *(const float4*)(Bg + j * 4);
    }

    const int NST = D / 32;   // 24
    for (int s = 0; s < NST; s++) {
        const int buf = s & 1;
        {
            unsigned* a  = As + buf * 128 * 36 + lr * 36 + lk;
            unsigned* bp = Bs + buf * 128 * 36 + lr * 36 + lk;
            #pragma unroll
            for (int j = 0; j < 4; j++) {
                int kb = s * 32 + lk + j * 4;
                float4 w3v = *(const float4*)(w3 + kb);
                float4 w1v = *(const float4*)(w1 + kb);
                float4 w2v = *(const float4*)(w2 + kb);
                cwacc += pa[j].x * w1v.x + pa[j].y * w1v.y
                       + pa[j].z * w1v.z + pa[j].w * w1v.w;
                qwacc += pb[j].x * w2v.x + pb[j].y * w2v.y
                       + pb[j].z * w2v.z + pb[j].w * w2v.w;
                uint4 av, bv;
                av.x = f2tf(pa[j].x * w3v.x); av.y = f2tf(pa[j].y * w3v.y);
                av.z = f2tf(pa[j].z * w3v.z); av.w = f2tf(pa[j].w * w3v.w);
                bv.x = f2tf(pb[j].x); bv.y = f2tf(pb[j].y);
                bv.z = f2tf(pb[j].z); bv.w = f2tf(pb[j].w);
                *(uint4*)(a  + j * 4) = av;
                *(uint4*)(bp + j * 4) = bv;
            }
        }
        __syncthreads();
        if (s + 1 < NST) {
            #pragma unroll
            for (int j = 0; j < 4; j++) {
                pa[j] = *(const float4*)(Ag + (s + 1) * 32 + j * 4);
                pb[j] = *(const float4*)(Bg + (s + 1) * 32 + j * 4);
            }
        }
        const unsigned* ab = As + buf * 128 * 36;
        const unsigned* bb = Bs + buf * 128 * 36;
        #pragma unroll
        for (int k8 = 0; k8 < 32; k8 += 8) {
            unsigned afr[2][4];
            #pragma unroll
            for (int mi = 0; mi < 2; mi++) {
                int r0 = wm + mi * 16 + g;
                afr[mi][0] = ab[r0 * 36 + k8 + tg];
                afr[mi][1] = ab[(r0 + 8) * 36 + k8 + tg];
                afr[mi][2] = ab[r0 * 36 + k8 + tg + 4];
                afr[mi][3] = ab[(r0 + 8) * 36 + k8 + tg + 4];
            }
            #pragma unroll
            for (int ni = 0; ni < 8; ni++) {
                int nb = wn + ni * 8 + g;
                unsigned bfr[2];
                bfr[0] = bb[nb * 36 + k8 + tg];
                bfr[1] = bb[nb * 36 + k8 + tg + 4];
                mma_tf32(acc[0][ni], afr[0], bfr);
                mma_tf32(acc[1][ni], afr[1], bfr);
            }
        }
    }

    // finish fused row dots: pair (t, t^1) holds the two halves of row lr
    cwacc += __shfl_xor_sync(~0u, cwacc, 1);
    qwacc += __shfl_xor_sync(~0u, qwacc, 1);
    if ((t & 1) == 0) { s_cw[lr] = cwacc; s_qw[lr] = qwacc; }
    __syncthreads();

    // epilogue: +cw1 +qw2, store sim, fused row-max -> g_Smax
    float qv0[8], qv1[8];
    #pragma unroll
    for (int ni = 0; ni < 8; ni++) {
        int col = wn + ni * 8 + 2 * tg;
        qv0[ni] = s_qw[col]; qv1[ni] = s_qw[col + 1];
    }
    #pragma unroll
    for (int mi = 0; mi < 2; mi++) {
        #pragma unroll
        for (int half = 0; half < 2; half++) {
            int rloc = wm + mi * 16 + g + half * 8;
            int row  = cm + rloc;
            float cw = s_cw[rloc];
            float* orow = g_sim + ((size_t)b * C + row) * Q + wn;
            float m = -INFINITY;
            #pragma unroll
            for (int ni = 0; ni < 8; ni++) {
                float v0 = acc[mi][ni][half * 2 + 0] + cw + qv0[ni];
                float v1 = acc[mi][ni][half * 2 + 1] + cw + qv1[ni];
                *(float2*)(orow + ni * 8 + 2 * tg) = make_float2(v0, v1);
                m = fmaxf(m, fmaxf(v0, v1));
            }
            m = fmaxf(m, __shfl_xor_sync(~0u, m, 1));
            m = fmaxf(m, __shfl_xor_sync(~0u, m, 2));
            if (tg == 0) red[(warp >> 2) * 128 + rloc] = m;
        }
    }
    __syncthreads();
    if (t < 128) g_Smax[b * C + cm + t] = fmaxf(red[t], red[128 + t]);
}

// ---------------- K2b: column softmax partials -------------------------------
__global__ void k_colpart(const int* __restrict__ qmask) {
    int b = blockIdx.x, ch = blockIdx.y;
    int q = threadIdx.x;
    float addend = (1.0f - (float)qmask[b * Q + q]) * NEG;
    const float* base = g_sim + ((size_t)b * C + ch * (C / NCH)) * Q + q;
    float m = -INFINITY;
    #pragma unroll 8
    for (int c = 0; c < C / NCH; c++) m = fmaxf(m, base[(size_t)c * Q] + addend);
    float s = 0.f;
    #pragma unroll 8
    for (int c = 0; c < C / NCH; c++) s += expf((base[(size_t)c * Q] + addend) - m);
    g_pmax[(b * NCH + ch) * Q + q] = m;
    g_psum[(b * NCH + ch) * Q + q] = s;
}

// ---------------- K2c+K3a merged: colfin (bx<B) / cdist (bx>=B) -------------
__global__ void k_finish(const int* __restrict__ cmask) {
    __shared__ float red[256];
    int bx = blockIdx.x;
    int t  = threadIdx.x;
    if (bx < B) {
        if (t < Q) {
            int b = bx, q = t;
            float pm[NCH], ps[NCH];
            float m = -INFINITY;
            #pragma unroll
            for (int ch = 0; ch < NCH; ch++) {
                pm[ch] = g_pmax[(b * NCH + ch) * Q + q];
                ps[ch] = g_psum[(b * NCH + ch) * Q + q];
                m = fmaxf(m, pm[ch]);
            }
            float s = 0.f;
            #pragma unroll
            for (int ch = 0; ch < NCH; ch++) s += ps[ch] * expf(pm[ch] - m);
            g_colmax[b * Q + q] = m;
            g_colinv[b * Q + q] = 1.0f / s;
        }
    } else {
        int b = bx - B;
        float v0 = g_Smax[b * C + t]       + (1.0f - (float)cmask[b * C + t]) * NEG;
        float v1 = g_Smax[b * C + 256 + t] + (1.0f - (float)cmask[b * C + 256 + t]) * NEG;
        red[t] = fmaxf(v0, v1);
        __syncthreads();
        for (int s = 128; s; s >>= 1) {
            if (t < s) red[t] = fmaxf(red[t], red[t + s]);
            __syncthreads();
        }
        float m = red[0];
        __syncthreads();
        float e0 = expf(v0 - m), e1 = expf(v1 - m);
        red[t] = e0 + e1;
        __syncthreads();
        for (int s = 128; s; s >>= 1) {
            if (t < s) red[t] += red[t + s];
            __syncthreads();
        }
        float inv = 1.0f / red[0];
        g_cdist[b * C + t]       = e0 * inv;
        g_cdist[b * C + 256 + t] = e1 * inv;
    }
}

// ---------------- K3b: c_dash[b,d] = sum_c dist[c]*C[b,c,d], 8 MLP streams ---
__global__ void k_cdash(const float* __restrict__ cont) {
    int b = blockIdx.x;
    int d = blockIdx.y * 256 + threadIdx.x;
    __shared__ float sd[C];
    for (int i = threadIdx.x; i < C; i += 256) sd[i] = g_cdist[b * C + i];
    __syncthreads();
    const float* cb = cont + (size_t)b * C * D + d;
    float a[8] = {0.f, 0.f, 0.f, 0.f, 0.f, 0.f, 0.f, 0.f};
    for (int c0 = 0; c0 < 64; c0++) {
        #pragma unroll
        for (int u = 0; u < 8; u++) {
            int c = c0 + u * 64;
            a[u] = fmaf(sd[c], cb[(size_t)c * D], a[u]);
        }
    }
    float s = ((a[0] + a[1]) + (a[2] + a[3])) + ((a[4] + a[5]) + (a[6] + a[7]));
    g_cdash[b * D + d] = s;
}

// ---------------- K4: c2q = P @ Q, P built once in smem, 6 d-tiles/block -----
// 128 blocks = 1 wave. smem: P[128][132] tf32, Bs[2][32][136] tf32, s_*[128]
__global__ __launch_bounds__(256) void k_c2q_mma(const float* __restrict__ cont,
                                                 const float* __restrict__ ques,
                                                 const int*   __restrict__ qmask,
                                                 float* __restrict__ out) {
    const int b  = blockIdx.z;
    const int cm = blockIdx.x * 128;
    extern __shared__ unsigned smemu[];
    unsigned* P  = smemu;                          // [128][132]
    unsigned* Bs = smemu + 128 * 132;              // [2][32][136]
    float* s_add = (float*)(Bs + 2 * 32 * 136);
    float* s_max = s_add + 128;
    float* s_inv = s_max + 128;

    const int t = threadIdx.x, lane = t & 31, warp = t >> 5;
    const int g = lane >> 2, tg = lane & 3;
    const int wm = (warp & 3) * 32;
    const int wn = (warp >> 2) * 64;

    if (t < Q) {
        s_add[t] = (1.0f - (float)qmask[b * Q + t]) * NEG;
        s_max[t] = g_colmax[b * Q + t];
        s_inv[t] = g_colinv[b * Q + t];
    }
    __syncthreads();

    // build P = tf32( exp((sim+add)-max)*inv ), one time
    const int lr = t >> 1;
    const int lk = (t & 1) * 16;
    {
        const float* simrow = g_sim + ((size_t)(b * C + cm + lr)) * Q + lk;
        #pragma unroll
        for (int sc = 0; sc < 4; sc++) {
            #pragma unroll
            for (int j = 0; j < 4; j++) {
                int q0 = sc * 32 + lk + j * 4;
                float4 sv = *(const float4*)(simrow + sc * 32 + j * 4);
                uint4 av;
                av.x = f2tf(expf((sv.x + s_add[q0+0]) - s_max[q0+0]) * s_inv[q0+0]);
                av.y = f2tf(expf((sv.y + s_add[q0+1]) - s_max[q0+1]) * s_inv[q0+1]);
                av.z = f2tf(expf((sv.z + s_add[q0+2]) - s_max[q0+2]) * s_inv[q0+2]);
                av.w = f2tf(expf((sv.w + s_add[q0+3]) - s_max[q0+3]) * s_inv[q0+3]);
                *(uint4*)(P + lr * 132 + q0) = av;
            }
        }
    }

    const int br = t >> 3;
    const int bd = (t & 7) * 4;
    const float* quesb = ques + (size_t)b * Q * D + bd;

    float4 pb[4];
    #pragma unroll
    for (int j = 0; j < 4; j++)
        pb[j] = *(const float4*)(quesb + (size_t)br * D + j * 32);

    __syncthreads();   // P + s_* visible

    for (int dn = 0; dn < 6; dn++) {
        float acc[2][8][4];
        #pragma unroll
        for (int i = 0; i < 2; i++)
            #pragma unroll
            for (int j = 0; j < 8; j++)
                #pragma unroll
                for (int k = 0; k < 4; k++) acc[i][j][k] = 0.f;

        #pragma unroll
        for (int sc = 0; sc < 4; sc++) {
            const int it  = dn * 4 + sc;
            const int buf = it & 1;
            {
                unsigned* bp = Bs + buf * 32 * 136 + br * 136 + bd;
                #pragma unroll
                for (int j = 0; j < 4; j++) {
                    uint4 bv;
                    bv.x = f2tf(pb[j].x); bv.y = f2tf(pb[j].y);
                    bv.z = f2tf(pb[j].z); bv.w = f2tf(pb[j].w);
                    *(uint4*)(bp + j * 32) = bv;
                }
            }
            if (it + 1 < 24) {
                int dn2 = (it + 1) >> 2, sc2 = (it + 1) & 3;
                #pragma unroll
                for (int j = 0; j < 4; j++)
                    pb[j] = *(const float4*)(quesb +
                            (size_t)(sc2 * 32 + br) * D + dn2 * 128 + j * 32);
            }
            __syncthreads();
            const unsigned* bb = Bs + buf * 32 * 136;
            #pragma unroll
            for (int k8 = 0; k8 < 32; k8 += 8) {
                const int kk = sc * 32 + k8;
                unsigned afr[2][4];
                #pragma unroll
                for (int mi = 0; mi < 2; mi++) {
                    int r0 = wm + mi * 16 + g;
                    afr[mi][0] = P[r0 * 132 + kk + tg];
                    afr[mi][1] = P[(r0 + 8) * 132 + kk + tg];
                    afr[mi][2] = P[r0 * 132 + kk + tg + 4];
                    afr[mi][3] = P[(r0 + 8) * 132 + kk + tg + 4];
                }
                #pragma unroll
                for (int ni = 0; ni < 8; ni++) {
                    int nb = wn + ni * 8 + g;
                    unsigned bfr[2];
                    bfr[0] = bb[(k8 + tg) * 136 + nb];
                    bfr[1] = bb[(k8 + tg + 4) * 136 + nb];
                    mma_tf32(acc[0][ni], afr[0], bfr);
                    mma_tf32(acc[1][ni], afr[1], bfr);
                }
            }
        }

        // epilogue for this d-tile: out = [ c | c2q | c*c2q | c*c_dash ]
        #pragma unroll
        for (int mi = 0; mi < 2; mi++) {
            #pragma unroll
            for (int half = 0; half < 2; half++) {
                int cc = cm + wm + mi * 16 + g + half * 8;
                const float* crow = cont + ((size_t)b * C + cc) * D + dn * 128;
                float* obase = out + ((size_t)b * C + cc) * (4 * D);
                #pragma unroll
                for (int ni = 0; ni < 8; ni++) {
                    int col = wn + ni * 8 + 2 * tg;
                    int dg  = dn * 128 + col;
                    float2 cv = *(const float2*)(crow + col);
                    float2 cd = *(const float2*)&g_cdash[b * D + dg];
                    float2 v  = make_float2(acc[mi][ni][half * 2 + 0],
                                            acc[mi][ni][half * 2 + 1]);
                    *(float2*)&obase[dg]         = cv;
                    *(float2*)&obase[D + dg]     = v;
                    *(float2*)&obase[2 * D + dg] = make_float2(cv.x * v.x, cv.y * v.y);
                    *(float2*)&obase[3 * D + dg] = make_float2(cv.x * cd.x, cv.y * cd.y);
                }
            }
        }
    }
}

// ---------------- launch -----------------------------------------------------
extern "C" void kernel_launch(void* const* d_in, const int* in_sizes, int n_in,
                              void* d_out, int out_size) {
    const float* cont  = (const float*)d_in[0];
    const int*   cmask = (const int*)d_in[1];
    const float* ques  = (const float*)d_in[2];
    const int*   qmask = (const int*)d_in[3];
    const float* SW    = (const float*)d_in[4];
    float* out = (float*)d_out;

    const int smem_sim = 4 * 128 * 36 * 4 + (256 + 128 + 128) * 4;        // 75776
    const int smem_c2q = (128 * 132 + 2 * 32 * 136) * 4 + 3 * 128 * 4;    // 103936
    cudaFuncSetAttribute(k_sim_mma, cudaFuncAttributeMaxDynamicSharedMemorySize, smem_sim);
    cudaFuncSetAttribute(k_c2q_mma, cudaFuncAttributeMaxDynamicSharedMemorySize, smem_c2q);

    k_sim_mma<<<dim3(C / 128, 1, B), 256, smem_sim>>>(cont, ques, SW);
    k_colpart<<<dim3(B, NCH), Q>>>(qmask);
    k_finish<<<2 * B, 256>>>(cmask);
    k_cdash<<<dim3(B, 3), 256>>>(cont);
    k_c2q_mma<<<dim3(C / 128, 1, B), 256, smem_c2q>>>(cont, ques, qmask, out);
}

// round 4
// speedup vs baseline: 1.7326x; 1.2185x over previous
#include <cuda_runtime.h>
#include <math.h>

#define B 32
#define C 512
#define Q 128
#define D 768
#define NEG (-1e30f)
#define NCH 16
#define NCC 8    // c-chunks for cdash partials

// ---------------- scratch ----------------------------------------------------
__device__ float g_sim[(size_t)B * C * Q];
__device__ float g_Smax[B * C];
__device__ float g_pmax[B * NCH * Q];
__device__ float g_psum[B * NCH * Q];
__device__ float g_colmax[B * Q];
__device__ float g_colinv[B * Q];
__device__ float g_cdist[B * C];
__device__ float g_cdash[B * D];
__device__ float g_cdashp[NCC][B * D];

// ---------------- tf32 helpers ----------------------------------------------
__device__ __forceinline__ unsigned f2tf(float f) {
    unsigned u; asm("cvt.rna.tf32.f32 %0, %1;" : "=r"(u) : "f"(f)); return u;
}
__device__ __forceinline__ void mma_tf32(float* d, const unsigned* a, const unsigned* b) {
    asm volatile("mma.sync.aligned.m16n8k8.row.col.f32.tf32.tf32.f32 "
                 "{%0,%1,%2,%3}, {%4,%5,%6,%7}, {%8,%9}, {%0,%1,%2,%3};"
                 : "+f"(d[0]), "+f"(d[1]), "+f"(d[2]), "+f"(d[3])
                 : "r"(a[0]), "r"(a[1]), "r"(a[2]), "r"(a[3]), "r"(b[0]), "r"(b[1]));
}

// ---------------- K1: sim = (c*w3)·qT + cw1 + qw2 (dots fused), S_max --------
__global__ __launch_bounds__(256) void k_sim_mma(const float* __restrict__ cont,
                                                 const float* __restrict__ ques,
                                                 const float* __restrict__ SW) {
    const int b  = blockIdx.z;
    const int cm = blockIdx.x * 128;
    extern __shared__ unsigned smemu[];
    unsigned* As = smemu;
    unsigned* Bs = smemu + 2 * 128 * 36;
    float*   red = (float*)(smemu + 4 * 128 * 36);
    float*  s_cw = red + 256;
    float*  s_qw = s_cw + 128;

    const int t = threadIdx.x, lane = t & 31, warp = t >> 5;
    const int g = lane >> 2, tg = lane & 3;
    const int wm = (warp & 3) * 32;
    const int wn = (warp >> 2) * 64;

    const float* w1 = SW;
    const float* w2 = SW + D;
    const float* w3 = SW + 2 * D;
    const int lr = t >> 1;
    const int lk = (t & 1) * 16;
    const float* Ag = cont + ((size_t)(b * C + cm + lr)) * D + lk;
    const float* Bg = ques + ((size_t)(b * Q + lr)) * D + lk;

    float acc[2][8][4];
    #pragma unroll
    for (int i = 0; i < 2; i++)
        #pragma unroll
        for (int j = 0; j < 8; j++)
            #pragma unroll
            for (int k = 0; k < 4; k++) acc[i][j][k] = 0.f;

    float cwacc = 0.f, qwacc = 0.f;

    float4 pa[4], pb[4];
    #pragma unroll
    for (int j = 0; j < 4; j++) {
        pa[j] = *(const float4*)(Ag + j * 4);
        pb[j] = *(const float4*)(Bg + j * 4);
    }

    const int NST = D / 32;   // 24
    for (int s = 0; s < NST; s++) {
        const int buf = s & 1;
        {
            unsigned* a  = As + buf * 128 * 36 + lr * 36 + lk;
            unsigned* bp = Bs + buf * 128 * 36 + lr * 36 + lk;
            #pragma unroll
            for (int j = 0; j < 4; j++) {
                int kb = s * 32 + lk + j * 4;
                float4 w3v = *(const float4*)(w3 + kb);
                float4 w1v = *(const float4*)(w1 + kb);
                float4 w2v = *(const float4*)(w2 + kb);
                cwacc += pa[j].x * w1v.x + pa[j].y * w1v.y
                       + pa[j].z * w1v.z + pa[j].w * w1v.w;
                qwacc += pb[j].x * w2v.x + pb[j].y * w2v.y
                       + pb[j].z * w2v.z + pb[j].w * w2v.w;
                uint4 av, bv;
                av.x = f2tf(pa[j].x * w3v.x); av.y = f2tf(pa[j].y * w3v.y);
                av.z = f2tf(pa[j].z * w3v.z); av.w = f2tf(pa[j].w * w3v.w);
                bv.x = f2tf(pb[j].x); bv.y = f2tf(pb[j].y);
                bv.z = f2tf(pb[j].z); bv.w = f2tf(pb[j].w);
                *(uint4*)(a  + j * 4) = av;
                *(uint4*)(bp + j * 4) = bv;
            }
        }
        __syncthreads();
        if (s + 1 < NST) {
            #pragma unroll
            for (int j = 0; j < 4; j++) {
                pa[j] = *(const float4*)(Ag + (s + 1) * 32 + j * 4);
                pb[j] = *(const float4*)(Bg + (s + 1) * 32 + j * 4);
            }
        }
        const unsigned* ab = As + buf * 128 * 36;
        const unsigned* bb = Bs + buf * 128 * 36;
        #pragma unroll
        for (int k8 = 0; k8 < 32; k8 += 8) {
            unsigned afr[2][4];
            #pragma unroll
            for (int mi = 0; mi < 2; mi++) {
                int r0 = wm + mi * 16 + g;
                afr[mi][0] = ab[r0 * 36 + k8 + tg];
                afr[mi][1] = ab[(r0 + 8) * 36 + k8 + tg];
                afr[mi][2] = ab[r0 * 36 + k8 + tg + 4];
                afr[mi][3] = ab[(r0 + 8) * 36 + k8 + tg + 4];
            }
            #pragma unroll
            for (int ni = 0; ni < 8; ni++) {
                int nb = wn + ni * 8 + g;
                unsigned bfr[2];
                bfr[0] = bb[nb * 36 + k8 + tg];
                bfr[1] = bb[nb * 36 + k8 + tg + 4];
                mma_tf32(acc[0][ni], afr[0], bfr);
                mma_tf32(acc[1][ni], afr[1], bfr);
            }
        }
    }

    cwacc += __shfl_xor_sync(~0u, cwacc, 1);
    qwacc += __shfl_xor_sync(~0u, qwacc, 1);
    if ((t & 1) == 0) { s_cw[lr] = cwacc; s_qw[lr] = qwacc; }
    __syncthreads();

    float qv0[8], qv1[8];
    #pragma unroll
    for (int ni = 0; ni < 8; ni++) {
        int col = wn + ni * 8 + 2 * tg;
        qv0[ni] = s_qw[col]; qv1[ni] = s_qw[col + 1];
    }
    #pragma unroll
    for (int mi = 0; mi < 2; mi++) {
        #pragma unroll
        for (int half = 0; half < 2; half++) {
            int rloc = wm + mi * 16 + g + half * 8;
            int row  = cm + rloc;
            float cw = s_cw[rloc];
            float* orow = g_sim + ((size_t)b * C + row) * Q + wn;
            float m = -INFINITY;
            #pragma unroll
            for (int ni = 0; ni < 8; ni++) {
                float v0 = acc[mi][ni][half * 2 + 0] + cw + qv0[ni];
                float v1 = acc[mi][ni][half * 2 + 1] + cw + qv1[ni];
                *(float2*)(orow + ni * 8 + 2 * tg) = make_float2(v0, v1);
                m = fmaxf(m, fmaxf(v0, v1));
            }
            m = fmaxf(m, __shfl_xor_sync(~0u, m, 1));
            m = fmaxf(m, __shfl_xor_sync(~0u, m, 2));
            if (tg == 0) red[(warp >> 2) * 128 + rloc] = m;
        }
    }
    __syncthreads();
    if (t < 128) g_Smax[b * C + cm + t] = fmaxf(red[t], red[128 + t]);
}

// ---------------- K2b: column softmax partials -------------------------------
__global__ void k_colpart(const int* __restrict__ qmask) {
    int b = blockIdx.x, ch = blockIdx.y;
    int q = threadIdx.x;
    float addend = (1.0f - (float)qmask[b * Q + q]) * NEG;
    const float* base = g_sim + ((size_t)b * C + ch * (C / NCH)) * Q + q;
    float m = -INFINITY;
    #pragma unroll 8
    for (int c = 0; c < C / NCH; c++) m = fmaxf(m, base[(size_t)c * Q] + addend);
    float s = 0.f;
    #pragma unroll 8
    for (int c = 0; c < C / NCH; c++) s += expf((base[(size_t)c * Q] + addend) - m);
    g_pmax[(b * NCH + ch) * Q + q] = m;
    g_psum[(b * NCH + ch) * Q + q] = s;
}

// ---------------- K2c+K3a merged: colfin (bx<B) / cdist (bx>=B) -------------
__global__ void k_finish(const int* __restrict__ cmask) {
    __shared__ float red[256];
    int bx = blockIdx.x;
    int t  = threadIdx.x;
    if (bx < B) {
        if (t < Q) {
            int b = bx, q = t;
            float pm[NCH], ps[NCH];
            float m = -INFINITY;
            #pragma unroll
            for (int ch = 0; ch < NCH; ch++) {
                pm[ch] = g_pmax[(b * NCH + ch) * Q + q];
                ps[ch] = g_psum[(b * NCH + ch) * Q + q];
                m = fmaxf(m, pm[ch]);
            }
            float s = 0.f;
            #pragma unroll
            for (int ch = 0; ch < NCH; ch++) s += ps[ch] * expf(pm[ch] - m);
            g_colmax[b * Q + q] = m;
            g_colinv[b * Q + q] = 1.0f / s;
        }
    } else {
        int b = bx - B;
        float v0 = g_Smax[b * C + t]       + (1.0f - (float)cmask[b * C + t]) * NEG;
        float v1 = g_Smax[b * C + 256 + t] + (1.0f - (float)cmask[b * C + 256 + t]) * NEG;
        red[t] = fmaxf(v0, v1);
        __syncthreads();
        for (int s = 128; s; s >>= 1) {
            if (t < s) red[t] = fmaxf(red[t], red[t + s]);
            __syncthreads();
        }
        float m = red[0];
        __syncthreads();
        float e0 = expf(v0 - m), e1 = expf(v1 - m);
        red[t] = e0 + e1;
        __syncthreads();
        for (int s = 128; s; s >>= 1) {
            if (t < s) red[t] += red[t + s];
            __syncthreads();
        }
        float inv = 1.0f / red[0];
        g_cdist[b * C + t]       = e0 * inv;
        g_cdist[b * C + 256 + t] = e1 * inv;
    }
}

// ---------------- K3b: cdash partials, grid (B,6,NCC) — full-chip ------------
__global__ void k_cdash_part(const float* __restrict__ cont) {
    int b = blockIdx.x, dch = blockIdx.y, cch = blockIdx.z;
    int d = dch * 128 + threadIdx.x;
    __shared__ float sd[C / NCC];
    if (threadIdx.x < C / NCC)
        sd[threadIdx.x] = g_cdist[b * C + cch * (C / NCC) + threadIdx.x];
    __syncthreads();
    const float* cb = cont + (size_t)(b * C + cch * (C / NCC)) * D + d;
    float a[8] = {0.f, 0.f, 0.f, 0.f, 0.f, 0.f, 0.f, 0.f};
    for (int c0 = 0; c0 < 8; c0++) {
        #pragma unroll
        for (int u = 0; u < 8; u++) {
            int c = u * 8 + c0;
            a[u] = fmaf(sd[c], cb[(size_t)c * D], a[u]);
        }
    }
    float s = ((a[0] + a[1]) + (a[2] + a[3])) + ((a[4] + a[5]) + (a[6] + a[7]));
    g_cdashp[cch][b * D + d] = s;
}

// ---------------- K3c: reduce cdash partials ---------------------------------
__global__ void k_cdash_red() {
    int b = blockIdx.x, dch = blockIdx.y;
    int d = dch * 128 + threadIdx.x;
    float s = 0.f;
    #pragma unroll
    for (int u = 0; u < NCC; u++) s += g_cdashp[u][b * D + d];
    g_cdash[b * D + d] = s;
}

// ---------------- K4: c2q = P @ Q, P built once in smem, 6 d-tiles/block -----
__global__ __launch_bounds__(256) void k_c2q_mma(const float* __restrict__ cont,
                                                 const float* __restrict__ ques,
                                                 const int*   __restrict__ qmask,
                                                 float* __restrict__ out) {
    const int b  = blockIdx.z;
    const int cm = blockIdx.x * 128;
    extern __shared__ unsigned smemu[];
    unsigned* P  = smemu;                          // [128][132]
    unsigned* Bs = smemu + 128 * 132;              // [2][32][136]
    float* s_add = (float*)(Bs + 2 * 32 * 136);
    float* s_max = s_add + 128;
    float* s_inv = s_max + 128;

    const int t = threadIdx.x, lane = t & 31, warp = t >> 5;
    const int g = lane >> 2, tg = lane & 3;
    const int wm = (warp & 3) * 32;
    const int wn = (warp >> 2) * 64;

    if (t < Q) {
        s_add[t] = (1.0f - (float)qmask[b * Q + t]) * NEG;
        s_max[t] = g_colmax[b * Q + t];
        s_inv[t] = g_colinv[b * Q + t];
    }
    __syncthreads();

    const int lr = t >> 1;
    const int lk = (t & 1) * 16;
    {
        const float* simrow = g_sim + ((size_t)(b * C + cm + lr)) * Q + lk;
        #pragma unroll
        for (int sc = 0; sc < 4; sc++) {
            #pragma unroll
            for (int j = 0; j < 4; j++) {
                int q0 = sc * 32 + lk + j * 4;
                float4 sv = *(const float4*)(simrow + sc * 32 + j * 4);
                uint4 av;
                av.x = f2tf(expf((sv.x + s_add[q0+0]) - s_max[q0+0]) * s_inv[q0+0]);
                av.y = f2tf(expf((sv.y + s_add[q0+1]) - s_max[q0+1]) * s_inv[q0+1]);
                av.z = f2tf(expf((sv.z + s_add[q0+2]) - s_max[q0+2]) * s_inv[q0+2]);
                av.w = f2tf(expf((sv.w + s_add[q0+3]) - s_max[q0+3]) * s_inv[q0+3]);
                *(uint4*)(P + lr * 132 + q0) = av;
            }
        }
    }

    const int br = t >> 3;
    const int bd = (t & 7) * 4;
    const float* quesb = ques + (size_t)b * Q * D + bd;

    float4 pb[4];
    #pragma unroll
    for (int j = 0; j < 4; j++)
        pb[j] = *(const float4*)(quesb + (size_t)br * D + j * 32);

    __syncthreads();

    for (int dn = 0; dn < 6; dn++) {
        float acc[2][8][4];
        #pragma unroll
        for (int i = 0; i < 2; i++)
            #pragma unroll
            for (int j = 0; j < 8; j++)
                #pragma unroll
                for (int k = 0; k < 4; k++) acc[i][j][k] = 0.f;

        #pragma unroll
        for (int sc = 0; sc < 4; sc++) {
            const int it  = dn * 4 + sc;
            const int buf = it & 1;
            {
                unsigned* bp = Bs + buf * 32 * 136 + br * 136 + bd;
                #pragma unroll
                for (int j = 0; j < 4; j++) {
                    uint4 bv;
                    bv.x = f2tf(pb[j].x); bv.y = f2tf(pb[j].y);
                    bv.z = f2tf(pb[j].z); bv.w = f2tf(pb[j].w);
                    *(uint4*)(bp + j * 32) = bv;
                }
            }
            if (it + 1 < 24) {
                int dn2 = (it + 1) >> 2, sc2 = (it + 1) & 3;
                #pragma unroll
                for (int j = 0; j < 4; j++)
                    pb[j] = *(const float4*)(quesb +
                            (size_t)(sc2 * 32 + br) * D + dn2 * 128 + j * 32);
            }
            __syncthreads();
            const unsigned* bb = Bs + buf * 32 * 136;
            #pragma unroll
            for (int k8 = 0; k8 < 32; k8 += 8) {
                const int kk = sc * 32 + k8;
                unsigned afr[2][4];
                #pragma unroll
                for (int mi = 0; mi < 2; mi++) {
                    int r0 = wm + mi * 16 + g;
                    afr[mi][0] = P[r0 * 132 + kk + tg];
                    afr[mi][1] = P[(r0 + 8) * 132 + kk + tg];
                    afr[mi][2] = P[r0 * 132 + kk + tg + 4];
                    afr[mi][3] = P[(r0 + 8) * 132 + kk + tg + 4];
                }
                #pragma unroll
                for (int ni = 0; ni < 8; ni++) {
                    int nb = wn + ni * 8 + g;
                    unsigned bfr[2];
                    bfr[0] = bb[(k8 + tg) * 136 + nb];
                    bfr[1] = bb[(k8 + tg + 4) * 136 + nb];
                    mma_tf32(acc[0][ni], afr[0], bfr);
                    mma_tf32(acc[1][ni], afr[1], bfr);
                }
            }
        }

        #pragma unroll
        for (int mi = 0; mi < 2; mi++) {
            #pragma unroll
            for (int half = 0; half < 2; half++) {
                int cc = cm + wm + mi * 16 + g + half * 8;
                const float* crow = cont + ((size_t)b * C + cc) * D + dn * 128;
                float* obase = out + ((size_t)b * C + cc) * (4 * D);
                #pragma unroll
                for (int ni = 0; ni < 8; ni++) {
                    int col = wn + ni * 8 + 2 * tg;
                    int dg  = dn * 128 + col;
                    float2 cv = *(const float2*)(crow + col);
                    float2 cd = *(const float2*)&g_cdash[b * D + dg];
                    float2 v  = make_float2(acc[mi][ni][half * 2 + 0],
                                            acc[mi][ni][half * 2 + 1]);
                    *(float2*)&obase[dg]         = cv;
                    *(float2*)&obase[D + dg]     = v;
                    *(float2*)&obase[2 * D + dg] = make_float2(cv.x * v.x, cv.y * v.y);
                    *(float2*)&obase[3 * D + dg] = make_float2(cv.x * cd.x, cv.y * cd.y);
                }
            }
        }
    }
}

// ---------------- launch -----------------------------------------------------
extern "C" void kernel_launch(void* const* d_in, const int* in_sizes, int n_in,
                              void* d_out, int out_size) {
    const float* cont  = (const float*)d_in[0];
    const int*   cmask = (const int*)d_in[1];
    const float* ques  = (const float*)d_in[2];
    const int*   qmask = (const int*)d_in[3];
    const float* SW    = (const float*)d_in[4];
    float* out = (float*)d_out;

    const int smem_sim = 4 * 128 * 36 * 4 + (256 + 128 + 128) * 4;        // 75776
    const int smem_c2q = (128 * 132 + 2 * 32 * 136) * 4 + 3 * 128 * 4;    // 103936
    cudaFuncSetAttribute(k_sim_mma, cudaFuncAttributeMaxDynamicSharedMemorySize, smem_sim);
    cudaFuncSetAttribute(k_c2q_mma, cudaFuncAttributeMaxDynamicSharedMemorySize, smem_c2q);

    k_sim_mma<<<dim3(C / 128, 1, B), 256, smem_sim>>>(cont, ques, SW);
    k_colpart<<<dim3(B, NCH), Q>>>(qmask);
    k_finish<<<2 * B, 256>>>(cmask);
    k_cdash_part<<<dim3(B, 6, NCC), 128>>>(cont);
    k_cdash_red<<<dim3(B, 6), 128>>>();
    k_c2q_mma<<<dim3(C / 128, 1, B), 256, smem_c2q>>>(cont, ques, qmask, out);
}

// round 5
// speedup vs baseline: 2.3395x; 1.3503x over previous
#include <cuda_runtime.h>
#include <math.h>

#define B 32
#define C 512
#define Q 128
#define D 768
#define NEG (-1e30f)
#define NCH 16
#define NCC 8

// ---------------- scratch ----------------------------------------------------
__device__ float g_sim[(size_t)B * C * Q];
__device__ float g_Smax[B * C];
__device__ float g_pmax[B * NCH * Q];
__device__ float g_psum[B * NCH * Q];
__device__ float g_colmax[B * Q];
__device__ float g_colinv[B * Q];
__device__ float g_cdist[B * C];
__device__ float g_cdashp[NCC][B * D];
__device__ __align__(16) unsigned g_quesT[(size_t)B * D * (Q / 2)];  // bf16 pairs along q

// ---------------- helpers ----------------------------------------------------
__device__ __forceinline__ unsigned pack_bf16(float lo, float hi) {
    unsigned r; asm("cvt.rn.bf16x2.f32 %0, %1, %2;" : "=r"(r) : "f"(hi), "f"(lo));
    return r;
}
__device__ __forceinline__ void mma_bf16(float* d, const unsigned* a, const unsigned* b) {
    asm volatile("mma.sync.aligned.m16n8k16.row.col.f32.bf16.bf16.f32 "
                 "{%0,%1,%2,%3}, {%4,%5,%6,%7}, {%8,%9}, {%0,%1,%2,%3};"
                 : "+f"(d[0]), "+f"(d[1]), "+f"(d[2]), "+f"(d[3])
                 : "r"(a[0]), "r"(a[1]), "r"(a[2]), "r"(a[3]), "r"(b[0]), "r"(b[1]));
}
__device__ __forceinline__ void cp16(void* smem_dst, const void* gsrc) {
    unsigned ds = (unsigned)__cvta_generic_to_shared(smem_dst);
    asm volatile("cp.async.cg.shared.global [%0], [%1], 16;" :: "r"(ds), "l"(gsrc));
}
__device__ __forceinline__ void cp_commit() { asm volatile("cp.async.commit_group;"); }
__device__ __forceinline__ void cp_wait0()  { asm volatile("cp.async.wait_group 0;"); }

// ---------------- K0: transpose ques -> quesT bf16 [b][d][q] -----------------
__global__ void k_trans(const float* __restrict__ ques) {
    __shared__ float tile[Q][33];
    int b = blockIdx.x, d0 = blockIdx.y * 32;
    int t = threadIdx.x;
    int q = t >> 1, cs = (t & 1) * 16;
    const float* src = ques + ((size_t)b * Q + q) * D + d0 + cs;
    #pragma unroll
    for (int j = 0; j < 4; j++) {
        float4 v = *(const float4*)(src + 4 * j);
        tile[q][cs + 4 * j + 0] = v.x; tile[q][cs + 4 * j + 1] = v.y;
        tile[q][cs + 4 * j + 2] = v.z; tile[q][cs + 4 * j + 3] = v.w;
    }
    __syncthreads();
    int dd = t >> 3, ws = (t & 7) * 8;
    unsigned w[8];
    #pragma unroll
    for (int j = 0; j < 8; j++) {
        int wq = ws + j;
        w[j] = pack_bf16(tile[2 * wq][dd], tile[2 * wq + 1][dd]);
    }
    unsigned* dst = g_quesT + ((size_t)(b * D + d0 + dd)) * 64 + ws;
    *(uint4*)(dst)     = make_uint4(w[0], w[1], w[2], w[3]);
    *(uint4*)(dst + 4) = make_uint4(w[4], w[5], w[6], w[7]);
}

// ---------------- K1: sim = (c*w3)·qT + cw1 + qw2 (bf16 mma), fused S_max ----
// smem: As[2][128][20], Bs[2][128][20] words; red[256], s_cw[128], s_qw[128]
__global__ __launch_bounds__(256) void k_sim_mma(const float* __restrict__ cont,
                                                 const float* __restrict__ ques,
                                                 const float* __restrict__ SW) {
    const int b  = blockIdx.z;
    const int cm = blockIdx.x * 128;
    extern __shared__ unsigned smemu[];
    unsigned* As = smemu;                    // [2][128][20]
    unsigned* Bs = smemu + 2 * 128 * 20;
    float*   red = (float*)(smemu + 4 * 128 * 20);
    float*  s_cw = red + 256;
    float*  s_qw = s_cw + 128;

    const int t = threadIdx.x, lane = t & 31, warp = t >> 5;
    const int g = lane >> 2, tg = lane & 3;
    const int wm = (warp & 3) * 32;
    const int wn = (warp >> 2) * 64;

    const float* w1 = SW;
    const float* w2 = SW + D;
    const float* w3 = SW + 2 * D;
    const int lr = t >> 1;
    const int lk = (t & 1) * 16;           // element offset within 32-k stage
    const int lw = (t & 1) * 8;            // word offset
    const float* Ag = cont + ((size_t)(b * C + cm + lr)) * D + lk;
    const float* Bg = ques + ((size_t)(b * Q + lr)) * D + lk;

    float acc[2][8][4];
    #pragma unroll
    for (int i = 0; i < 2; i++)
        #pragma unroll
        for (int j = 0; j < 8; j++)
            #pragma unroll
            for (int k = 0; k < 4; k++) acc[i][j][k] = 0.f;

    float cwacc = 0.f, qwacc = 0.f;

    float4 pa[4], pb[4];
    #pragma unroll
    for (int j = 0; j < 4; j++) {
        pa[j] = *(const float4*)(Ag + j * 4);
        pb[j] = *(const float4*)(Bg + j * 4);
    }

    const int NST = D / 32;   // 24
    for (int s = 0; s < NST; s++) {
        const int buf = s & 1;
        {
            unsigned ua[8], ub[8];
            #pragma unroll
            for (int j = 0; j < 4; j++) {
                int kb = s * 32 + lk + j * 4;
                float4 w3v = *(const float4*)(w3 + kb);
                float4 w1v = *(const float4*)(w1 + kb);
                float4 w2v = *(const float4*)(w2 + kb);
                cwacc += pa[j].x * w1v.x + pa[j].y * w1v.y
                       + pa[j].z * w1v.z + pa[j].w * w1v.w;
                qwacc += pb[j].x * w2v.x + pb[j].y * w2v.y
                       + pb[j].z * w2v.z + pb[j].w * w2v.w;
                ua[2*j]   = pack_bf16(pa[j].x * w3v.x, pa[j].y * w3v.y);
                ua[2*j+1] = pack_bf16(pa[j].z * w3v.z, pa[j].w * w3v.w);
                ub[2*j]   = pack_bf16(pb[j].x, pb[j].y);
                ub[2*j+1] = pack_bf16(pb[j].z, pb[j].w);
            }
            unsigned* a  = As + buf * 128 * 20 + lr * 20 + lw;
            unsigned* bp = Bs + buf * 128 * 20 + lr * 20 + lw;
            *(uint4*)(a)      = make_uint4(ua[0], ua[1], ua[2], ua[3]);
            *(uint4*)(a + 4)  = make_uint4(ua[4], ua[5], ua[6], ua[7]);
            *(uint4*)(bp)     = make_uint4(ub[0], ub[1], ub[2], ub[3]);
            *(uint4*)(bp + 4) = make_uint4(ub[4], ub[5], ub[6], ub[7]);
        }
        __syncthreads();
        if (s + 1 < NST) {
            #pragma unroll
            for (int j = 0; j < 4; j++) {
                pa[j] = *(const float4*)(Ag + (s + 1) * 32 + j * 4);
                pb[j] = *(const float4*)(Bg + (s + 1) * 32 + j * 4);
            }
        }
        const unsigned* ab = As + buf * 128 * 20;
        const unsigned* bb = Bs + buf * 128 * 20;
        #pragma unroll
        for (int h = 0; h < 2; h++) {       // two k16 steps per 32-k stage
            const int kp = h * 8;
            unsigned afr[2][4];
            #pragma unroll
            for (int mi = 0; mi < 2; mi++) {
                int r0 = wm + mi * 16 + g;
                afr[mi][0] = ab[r0 * 20 + kp + tg];
                afr[mi][1] = ab[(r0 + 8) * 20 + kp + tg];
                afr[mi][2] = ab[r0 * 20 + kp + tg + 4];
                afr[mi][3] = ab[(r0 + 8) * 20 + kp + tg + 4];
            }
            #pragma unroll
            for (int ni = 0; ni < 8; ni++) {
                int nb = wn + ni * 8 + g;
                unsigned bfr[2];
                bfr[0] = bb[nb * 20 + kp + tg];
                bfr[1] = bb[nb * 20 + kp + tg + 4];
                mma_bf16(acc[0][ni], afr[0], bfr);
                mma_bf16(acc[1][ni], afr[1], bfr);
            }
        }
        __syncthreads();
    }

    cwacc += __shfl_xor_sync(~0u, cwacc, 1);
    qwacc += __shfl_xor_sync(~0u, qwacc, 1);
    if ((t & 1) == 0) { s_cw[lr] = cwacc; s_qw[lr] = qwacc; }
    __syncthreads();

    float qv0[8], qv1[8];
    #pragma unroll
    for (int ni = 0; ni < 8; ni++) {
        int col = wn + ni * 8 + 2 * tg;
        qv0[ni] = s_qw[col]; qv1[ni] = s_qw[col + 1];
    }
    #pragma unroll
    for (int mi = 0; mi < 2; mi++) {
        #pragma unroll
        for (int half = 0; half < 2; half++) {
            int rloc = wm + mi * 16 + g + half * 8;
            int row  = cm + rloc;
            float cw = s_cw[rloc];
            float* orow = g_sim + ((size_t)b * C + row) * Q + wn;
            float m = -INFINITY;
            #pragma unroll
            for (int ni = 0; ni < 8; ni++) {
                float v0 = acc[mi][ni][half * 2 + 0] + cw + qv0[ni];
                float v1 = acc[mi][ni][half * 2 + 1] + cw + qv1[ni];
                *(float2*)(orow + ni * 8 + 2 * tg) = make_float2(v0, v1);
                m = fmaxf(m, fmaxf(v0, v1));
            }
            m = fmaxf(m, __shfl_xor_sync(~0u, m, 1));
            m = fmaxf(m, __shfl_xor_sync(~0u, m, 2));
            if (tg == 0) red[(warp >> 2) * 128 + rloc] = m;
        }
    }
    __syncthreads();
    if (t < 128) g_Smax[b * C + cm + t] = fmaxf(red[t], red[128 + t]);
}

// ---------------- K2b: column softmax partials -------------------------------
__global__ void k_colpart(const int* __restrict__ qmask) {
    int b = blockIdx.x, ch = blockIdx.y;
    int q = threadIdx.x;
    float addend = (1.0f - (float)qmask[b * Q + q]) * NEG;
    const float* base = g_sim + ((size_t)b * C + ch * (C / NCH)) * Q + q;
    float m = -INFINITY;
    #pragma unroll 8
    for (int c = 0; c < C / NCH; c++) m = fmaxf(m, base[(size_t)c * Q] + addend);
    float s = 0.f;
    #pragma unroll 8
    for (int c = 0; c < C / NCH; c++) s += expf((base[(size_t)c * Q] + addend) - m);
    g_pmax[(b * NCH + ch) * Q + q] = m;
    g_psum[(b * NCH + ch) * Q + q] = s;
}

// ---------------- K2c+K3a merged ---------------------------------------------
__global__ void k_finish(const int* __restrict__ cmask) {
    __shared__ float red[256];
    int bx = blockIdx.x;
    int t  = threadIdx.x;
    if (bx < B) {
        if (t < Q) {
            int b = bx, q = t;
            float pm[NCH], ps[NCH];
            float m = -INFINITY;
            #pragma unroll
            for (int ch = 0; ch < NCH; ch++) {
                pm[ch] = g_pmax[(b * NCH + ch) * Q + q];
                ps[ch] = g_psum[(b * NCH + ch) * Q + q];
                m = fmaxf(m, pm[ch]);
            }
            float s = 0.f;
            #pragma unroll
            for (int ch = 0; ch < NCH; ch++) s += ps[ch] * expf(pm[ch] - m);
            g_colmax[b * Q + q] = m;
            g_colinv[b * Q + q] = 1.0f / s;
        }
    } else {
        int b = bx - B;
        float v0 = g_Smax[b * C + t]       + (1.0f - (float)cmask[b * C + t]) * NEG;
        float v1 = g_Smax[b * C + 256 + t] + (1.0f - (float)cmask[b * C + 256 + t]) * NEG;
        red[t] = fmaxf(v0, v1);
        __syncthreads();
        for (int s = 128; s; s >>= 1) {
            if (t < s) red[t] = fmaxf(red[t], red[t + s]);
            __syncthreads();
        }
        float m = red[0];
        __syncthreads();
        float e0 = expf(v0 - m), e1 = expf(v1 - m);
        red[t] = e0 + e1;
        __syncthreads();
        for (int s = 128; s; s >>= 1) {
            if (t < s) red[t] += red[t + s];
            __syncthreads();
        }
        float inv = 1.0f / red[0];
        g_cdist[b * C + t]       = e0 * inv;
        g_cdist[b * C + 256 + t] = e1 * inv;
    }
}

// ---------------- K3b: cdash partials ----------------------------------------
__global__ void k_cdash_part(const float* __restrict__ cont) {
    int b = blockIdx.x, dch = blockIdx.y, cch = blockIdx.z;
    int d = dch * 128 + threadIdx.x;
    __shared__ float sd[C / NCC];
    if (threadIdx.x < C / NCC)
        sd[threadIdx.x] = g_cdist[b * C + cch * (C / NCC) + threadIdx.x];
    __syncthreads();
    const float* cb = cont + (size_t)(b * C + cch * (C / NCC)) * D + d;
    float a[8] = {0.f, 0.f, 0.f, 0.f, 0.f, 0.f, 0.f, 0.f};
    for (int c0 = 0; c0 < 8; c0++) {
        #pragma unroll
        for (int u = 0; u < 8; u++) {
            int c = u * 8 + c0;
            a[u] = fmaf(sd[c], cb[(size_t)c * D], a[u]);
        }
    }
    float s = ((a[0] + a[1]) + (a[2] + a[3])) + ((a[4] + a[5]) + (a[6] + a[7]));
    g_cdashp[cch][b * D + d] = s;
}

// ---------------- K4: c2q = P @ quesT (bf16), cp.async B, fused epilogue -----
// smem words: P[128][68], Bs[2][128][68]; floats: s_add/max/inv[128], s_cdash[768]
__global__ __launch_bounds__(256) void k_c2q_mma(const float* __restrict__ cont,
                                                 const int*   __restrict__ qmask,
                                                 float* __restrict__ out) {
    const int b  = blockIdx.z;
    const int cm = blockIdx.x * 128;
    extern __shared__ unsigned smemu[];
    unsigned* P  = smemu;                      // 128*68
    unsigned* Bs = smemu + 128 * 68;           // 2*128*68
    float* s_add   = (float*)(Bs + 2 * 128 * 68);
    float* s_max   = s_add + 128;
    float* s_inv   = s_max + 128;
    float* s_cdash = s_inv + 128;              // 768

    const int t = threadIdx.x, lane = t & 31, warp = t >> 5;
    const int g = lane >> 2, tg = lane & 3;
    const int wm = (warp & 3) * 32;
    const int wn = (warp >> 2) * 64;

    if (t < Q) {
        s_add[t] = (1.0f - (float)qmask[b * Q + t]) * NEG;
        s_max[t] = g_colmax[b * Q + t];
        s_inv[t] = g_colinv[b * Q + t];
    }
    for (int d = t; d < D; d += 256) {
        float s = 0.f;
        #pragma unroll
        for (int u = 0; u < NCC; u++) s += g_cdashp[u][b * D + d];
        s_cdash[d] = s;
    }
    __syncthreads();   // s_add/max/inv ready for P build

    // build P = bf16( exp((sim+add)-max)*inv )
    const int lr = t >> 1;
    const int lk = (t & 1) * 16;
    {
        const float* simrow = g_sim + ((size_t)(b * C + cm + lr)) * Q + lk;
        #pragma unroll
        for (int sc = 0; sc < 4; sc++) {
            #pragma unroll
            for (int j = 0; j < 4; j++) {
                int q0 = sc * 32 + lk + j * 4;
                float4 sv = *(const float4*)(simrow + sc * 32 + j * 4);
                float e0 = expf((sv.x + s_add[q0+0]) - s_max[q0+0]) * s_inv[q0+0];
                float e1 = expf((sv.y + s_add[q0+1]) - s_max[q0+1]) * s_inv[q0+1];
                float e2 = expf((sv.z + s_add[q0+2]) - s_max[q0+2]) * s_inv[q0+2];
                float e3 = expf((sv.w + s_add[q0+3]) - s_max[q0+3]) * s_inv[q0+3];
                *(uint2*)(P + lr * 68 + (q0 >> 1)) =
                    make_uint2(pack_bf16(e0, e1), pack_bf16(e2, e3));
            }
        }
    }

    // B fill helper state
    const int fr = t >> 1;                 // row (n = d within tile)
    const int fw = (t & 1) * 32;           // word offset within 64-word row
    const unsigned* qT = g_quesT + (size_t)b * D * 64;

    // issue tile 0
    {
        const unsigned* src = qT + (size_t)(0 * 128 + fr) * 64 + fw;
        unsigned* dst = Bs + 0 * 128 * 68 + fr * 68 + fw;
        #pragma unroll
        for (int j = 0; j < 8; j++) cp16(dst + 4 * j, src + 4 * j);
        cp_commit();
    }

    for (int dn = 0; dn < 6; dn++) {
        const int buf = dn & 1;
        cp_wait0();
        __syncthreads();   // Bs[buf] ready; also covers P on dn==0; guards buf reuse
        if (dn + 1 < 6) {
            const unsigned* src = qT + (size_t)((dn + 1) * 128 + fr) * 64 + fw;
            unsigned* dst = Bs + (buf ^ 1) * 128 * 68 + fr * 68 + fw;
            #pragma unroll
            for (int j = 0; j < 8; j++) cp16(dst + 4 * j, src + 4 * j);
            cp_commit();
        }

        float acc[2][8][4];
        #pragma unroll
        for (int i = 0; i < 2; i++)
            #pragma unroll
            for (int j = 0; j < 8; j++)
                #pragma unroll
                for (int k = 0; k < 4; k++) acc[i][j][k] = 0.f;

        const unsigned* bb = Bs + buf * 128 * 68;
        #pragma unroll
        for (int kk = 0; kk < 8; kk++) {   // 8 k16 steps (K=128)
            const int kp = kk * 8;
            unsigned afr[2][4];
            #pragma unroll
            for (int mi = 0; mi < 2; mi++) {
                int r0 = wm + mi * 16 + g;
                afr[mi][0] = P[r0 * 68 + kp + tg];
                afr[mi][1] = P[(r0 + 8) * 68 + kp + tg];
                afr[mi][2] = P[r0 * 68 + kp + tg + 4];
                afr[mi][3] = P[(r0 + 8) * 68 + kp + tg + 4];
            }
            #pragma unroll
            for (int ni = 0; ni < 8; ni++) {
                int nb = wn + ni * 8 + g;
                unsigned bfr[2];
                bfr[0] = bb[nb * 68 + kp + tg];
                bfr[1] = bb[nb * 68 + kp + tg + 4];
                mma_bf16(acc[0][ni], afr[0], bfr);
                mma_bf16(acc[1][ni], afr[1], bfr);
            }
        }

        // epilogue: out = [ c | c2q | c*c2q | c*c_dash ]
        #pragma unroll
        for (int mi = 0; mi < 2; mi++) {
            #pragma unroll
            for (int half = 0; half < 2; half++) {
                int cc = cm + wm + mi * 16 + g + half * 8;
                const float* crow = cont + ((size_t)b * C + cc) * D + dn * 128;
                float* obase = out + ((size_t)b * C + cc) * (4 * D);
                #pragma unroll
                for (int ni = 0; ni < 8; ni++) {
                    int col = wn + ni * 8 + 2 * tg;
                    int dg  = dn * 128 + col;
                    float2 cv = *(const float2*)(crow + col);
                    float2 cd = *(const float2*)&s_cdash[dg];
                    float2 v  = make_float2(acc[mi][ni][half * 2 + 0],
                                            acc[mi][ni][half * 2 + 1]);
                    *(float2*)&obase[dg]         = cv;
                    *(float2*)&obase[D + dg]     = v;
                    *(float2*)&obase[2 * D + dg] = make_float2(cv.x * v.x, cv.y * v.y);
                    *(float2*)&obase[3 * D + dg] = make_float2(cv.x * cd.x, cv.y * cd.y);
                }
            }
        }
    }
}

// ---------------- launch -----------------------------------------------------
extern "C" void kernel_launch(void* const* d_in, const int* in_sizes, int n_in,
                              void* d_out, int out_size) {
    const float* cont  = (const float*)d_in[0];
    const int*   cmask = (const int*)d_in[1];
    const float* ques  = (const float*)d_in[2];
    const int*   qmask = (const int*)d_in[3];
    const float* SW    = (const float*)d_in[4];
    float* out = (float*)d_out;

    const int smem_sim = 4 * 128 * 20 * 4 + (256 + 128 + 128) * 4;        // 43008
    const int smem_c2q = (128 * 68 + 2 * 128 * 68) * 4 + (3 * 128 + 768) * 4;  // 109056
    cudaFuncSetAttribute(k_sim_mma, cudaFuncAttributeMaxDynamicSharedMemorySize, smem_sim);
    cudaFuncSetAttribute(k_c2q_mma, cudaFuncAttributeMaxDynamicSharedMemorySize, smem_c2q);

    k_trans<<<dim3(B, D / 32), 256>>>(ques);
    k_sim_mma<<<dim3(C / 128, 1, B), 256, smem_sim>>>(cont, ques, SW);
    k_colpart<<<dim3(B, NCH), Q>>>(qmask);
    k_finish<<<2 * B, 256>>>(cmask);
    k_cdash_part<<<dim3(B, 6, NCC), 128>>>(cont);
    k_c2q_mma<<<dim3(C / 128, 1, B), 256, smem_c2q>>>(cont, qmask, out);
}

// round 7
// speedup vs baseline: 2.4758x; 1.0582x over previous
#include <cuda_runtime.h>
#include <math.h>

#define B 32
#define C 512
#define Q 128
#define D 768
#define NEG (-1e30f)
#define NCH 16
#define NCC 8

// ---------------- scratch ----------------------------------------------------
__device__ float g_sim[(size_t)B * C * Q];
__device__ float g_Smax[B * C];
__device__ float g_pmax[B * NCH * Q];
__device__ float g_psum[B * NCH * Q];
__device__ float g_cdist[B * C];
__device__ float g_cdashp[NCC][B * D];
__device__ __align__(16) unsigned g_quesT[(size_t)B * D * (Q / 2)];

// ---------------- helpers ----------------------------------------------------
__device__ __forceinline__ unsigned pack_bf16(float lo, float hi) {
    unsigned r; asm("cvt.rn.bf16x2.f32 %0, %1, %2;" : "=r"(r) : "f"(hi), "f"(lo));
    return r;
}
__device__ __forceinline__ void mma_bf16(float* d, const unsigned* a, const unsigned* b) {
    asm volatile("mma.sync.aligned.m16n8k16.row.col.f32.bf16.bf16.f32 "
                 "{%0,%1,%2,%3}, {%4,%5,%6,%7}, {%8,%9}, {%0,%1,%2,%3};"
                 : "+f"(d[0]), "+f"(d[1]), "+f"(d[2]), "+f"(d[3])
                 : "r"(a[0]), "r"(a[1]), "r"(a[2]), "r"(a[3]), "r"(b[0]), "r"(b[1]));
}
__device__ __forceinline__ void ldsm4(unsigned* r, unsigned addr) {
    asm volatile("ldmatrix.sync.aligned.m8n8.x4.shared.b16 {%0,%1,%2,%3}, [%4];"
                 : "=r"(r[0]), "=r"(r[1]), "=r"(r[2]), "=r"(r[3]) : "r"(addr));
}
__device__ __forceinline__ void cp16(void* smem_dst, const void* gsrc) {
    unsigned ds = (unsigned)__cvta_generic_to_shared(smem_dst);
    asm volatile("cp.async.cg.shared.global [%0], [%1], 16;" :: "r"(ds), "l"(gsrc));
}
__device__ __forceinline__ void cp_commit() { asm volatile("cp.async.commit_group;"); }
__device__ __forceinline__ void cp_wait0()  { asm volatile("cp.async.wait_group 0;"); }

// ---------------- K0: transpose ques -> quesT bf16 [b][d][q] -----------------
__global__ void k_trans(const float* __restrict__ ques) {
    __shared__ float tile[Q][33];
    int b = blockIdx.x, d0 = blockIdx.y * 32;
    int t = threadIdx.x;
    int q = t >> 1, cs = (t & 1) * 16;
    const float* src = ques + ((size_t)b * Q + q) * D + d0 + cs;
    #pragma unroll
    for (int j = 0; j < 4; j++) {
        float4 v = *(const float4*)(src + 4 * j);
        tile[q][cs + 4 * j + 0] = v.x; tile[q][cs + 4 * j + 1] = v.y;
        tile[q][cs + 4 * j + 2] = v.z; tile[q][cs + 4 * j + 3] = v.w;
    }
    __syncthreads();
    int dd = t >> 3, ws = (t & 7) * 8;
    unsigned w[8];
    #pragma unroll
    for (int j = 0; j < 8; j++) {
        int wq = ws + j;
        w[j] = pack_bf16(tile[2 * wq][dd], tile[2 * wq + 1][dd]);
    }
    unsigned* dst = g_quesT + ((size_t)(b * D + d0 + dd)) * 64 + ws;
    *(uint4*)(dst)     = make_uint4(w[0], w[1], w[2], w[3]);
    *(uint4*)(dst + 4) = make_uint4(w[4], w[5], w[6], w[7]);
}

// ---------------- K1: sim = (c*w3)·qT + cw1 + qw2 (bf16 mma + LDSM) ----------
__global__ __launch_bounds__(256) void k_sim_mma(const float* __restrict__ cont,
                                                 const float* __restrict__ ques,
                                                 const float* __restrict__ SW) {
    const int b  = blockIdx.z;
    const int cm = blockIdx.x * 128;
    extern __shared__ unsigned smemu[];
    unsigned* As = smemu;                    // [2][128][20]
    unsigned* Bs = smemu + 2 * 128 * 20;
    float*   red = (float*)(smemu + 4 * 128 * 20);
    float*  s_cw = red + 256;
    float*  s_qw = s_cw + 128;

    const int t = threadIdx.x, lane = t & 31, warp = t >> 5;
    const int g = lane >> 2, tg = lane & 3;
    const int wm = (warp & 3) * 32;
    const int wn = (warp >> 2) * 64;

    // LDSM per-lane offsets
    const int rA = (lane & 7) + (lane & 8);
    const int cA = (lane & 16) >> 2;            // +4 words on hi half
    const int rB = (lane & 7) + ((lane & 16) >> 1);
    const int cB = (lane & 8) >> 1;
    const unsigned aSh = (unsigned)__cvta_generic_to_shared(As);
    const unsigned bSh = (unsigned)__cvta_generic_to_shared(Bs);
    unsigned offA0 = ((wm + rA) * 20 + cA) * 4;
    unsigned offA1 = offA0 + 16 * 20 * 4;
    unsigned offB[4];
    #pragma unroll
    for (int p = 0; p < 4; p++) offB[p] = ((wn + p * 16 + rB) * 20 + cB) * 4;

    const float* w1 = SW;
    const float* w2 = SW + D;
    const float* w3 = SW + 2 * D;
    const int lr = t >> 1;
    const int lk = (t & 1) * 16;
    const int lw = (t & 1) * 8;
    const float* Ag = cont + ((size_t)(b * C + cm + lr)) * D + lk;
    const float* Bg = ques + ((size_t)(b * Q + lr)) * D + lk;

    float acc[2][8][4];
    #pragma unroll
    for (int i = 0; i < 2; i++)
        #pragma unroll
        for (int j = 0; j < 8; j++)
            #pragma unroll
            for (int k = 0; k < 4; k++) acc[i][j][k] = 0.f;

    float cwacc = 0.f, qwacc = 0.f;

    float4 pa[4], pb[4];
    #pragma unroll
    for (int j = 0; j < 4; j++) {
        pa[j] = *(const float4*)(Ag + j * 4);
        pb[j] = *(const float4*)(Bg + j * 4);
    }

    const int NST = D / 32;   // 24
    for (int s = 0; s < NST; s++) {
        const int buf = s & 1;
        const unsigned bufOff = (unsigned)buf * 128 * 20 * 4;
        {
            unsigned ua[8], ub[8];
            #pragma unroll
            for (int j = 0; j < 4; j++) {
                int kb = s * 32 + lk + j * 4;
                float4 w3v = *(const float4*)(w3 + kb);
                float4 w1v = *(const float4*)(w1 + kb);
                float4 w2v = *(const float4*)(w2 + kb);
                cwacc += pa[j].x * w1v.x + pa[j].y * w1v.y
                       + pa[j].z * w1v.z + pa[j].w * w1v.w;
                qwacc += pb[j].x * w2v.x + pb[j].y * w2v.y
                       + pb[j].z * w2v.z + pb[j].w * w2v.w;
                ua[2*j]   = pack_bf16(pa[j].x * w3v.x, pa[j].y * w3v.y);
                ua[2*j+1] = pack_bf16(pa[j].z * w3v.z, pa[j].w * w3v.w);
                ub[2*j]   = pack_bf16(pb[j].x, pb[j].y);
                ub[2*j+1] = pack_bf16(pb[j].z, pb[j].w);
            }
            unsigned* a  = As + buf * 128 * 20 + lr * 20 + lw;
            unsigned* bp = Bs + buf * 128 * 20 + lr * 20 + lw;
            *(uint4*)(a)      = make_uint4(ua[0], ua[1], ua[2], ua[3]);
            *(uint4*)(a + 4)  = make_uint4(ua[4], ua[5], ua[6], ua[7]);
            *(uint4*)(bp)     = make_uint4(ub[0], ub[1], ub[2], ub[3]);
            *(uint4*)(bp + 4) = make_uint4(ub[4], ub[5], ub[6], ub[7]);
        }
        __syncthreads();
        if (s + 1 < NST) {
            #pragma unroll
            for (int j = 0; j < 4; j++) {
                pa[j] = *(const float4*)(Ag + (s + 1) * 32 + j * 4);
                pb[j] = *(const float4*)(Bg + (s + 1) * 32 + j * 4);
            }
        }
        #pragma unroll
        for (int h = 0; h < 2; h++) {
            const unsigned koff = bufOff + h * 8 * 4;
            unsigned afr[2][4];
            ldsm4(afr[0], aSh + koff + offA0);
            ldsm4(afr[1], aSh + koff + offA1);
            #pragma unroll
            for (int p = 0; p < 4; p++) {
                unsigned bfr[4];
                ldsm4(bfr, bSh + koff + offB[p]);
                mma_bf16(acc[0][2*p],   afr[0], bfr);
                mma_bf16(acc[1][2*p],   afr[1], bfr);
                mma_bf16(acc[0][2*p+1], afr[0], bfr + 2);
                mma_bf16(acc[1][2*p+1], afr[1], bfr + 2);
            }
        }
        // no trailing barrier: next stage's post-STS barrier orders buffer reuse
    }

    cwacc += __shfl_xor_sync(~0u, cwacc, 1);
    qwacc += __shfl_xor_sync(~0u, qwacc, 1);
    if ((t & 1) == 0) { s_cw[lr] = cwacc; s_qw[lr] = qwacc; }
    __syncthreads();

    float qv0[8], qv1[8];
    #pragma unroll
    for (int ni = 0; ni < 8; ni++) {
        int col = wn + ni * 8 + 2 * tg;
        qv0[ni] = s_qw[col]; qv1[ni] = s_qw[col + 1];
    }
    #pragma unroll
    for (int mi = 0; mi < 2; mi++) {
        #pragma unroll
        for (int half = 0; half < 2; half++) {
            int rloc = wm + mi * 16 + g + half * 8;
            int row  = cm + rloc;
            float cw = s_cw[rloc];
            float* orow = g_sim + ((size_t)b * C + row) * Q + wn;
            float m = -INFINITY;
            #pragma unroll
            for (int ni = 0; ni < 8; ni++) {
                float v0 = acc[mi][ni][half * 2 + 0] + cw + qv0[ni];
                float v1 = acc[mi][ni][half * 2 + 1] + cw + qv1[ni];
                *(float2*)(orow + ni * 8 + 2 * tg) = make_float2(v0, v1);
                m = fmaxf(m, fmaxf(v0, v1));
            }
            m = fmaxf(m, __shfl_xor_sync(~0u, m, 1));
            m = fmaxf(m, __shfl_xor_sync(~0u, m, 2));
            if (tg == 0) red[(warp >> 2) * 128 + rloc] = m;
        }
    }
    __syncthreads();
    if (t < 128) g_Smax[b * C + cm + t] = fmaxf(red[t], red[128 + t]);
}

// ---------------- K2: colpart chunks (y<NCH) + cdist (y==NCH) ----------------
__global__ void k_mid(const int* __restrict__ qmask, const int* __restrict__ cmask) {
    __shared__ float red[128];
    const int b = blockIdx.x, y = blockIdx.y;
    const int t = threadIdx.x;   // 128
    if (y < NCH) {
        float addend = (1.0f - (float)qmask[b * Q + t]) * NEG;
        const float* base = g_sim + ((size_t)b * C + y * (C / NCH)) * Q + t;
        float v[C / NCH];
        float m = -INFINITY;
        #pragma unroll
        for (int c = 0; c < C / NCH; c++) {
            v[c] = base[(size_t)c * Q] + addend;
            m = fmaxf(m, v[c]);
        }
        float s = 0.f;
        #pragma unroll
        for (int c = 0; c < C / NCH; c++) s += __expf(v[c] - m);
        g_pmax[(b * NCH + y) * Q + t] = m;
        g_psum[(b * NCH + y) * Q + t] = s;
    } else {
        float v[4];
        #pragma unroll
        for (int j = 0; j < 4; j++) {
            int c = j * 128 + t;
            v[j] = g_Smax[b * C + c] + (1.0f - (float)cmask[b * C + c]) * NEG;
        }
        float m = fmaxf(fmaxf(v[0], v[1]), fmaxf(v[2], v[3]));
        red[t] = m;
        __syncthreads();
        for (int s = 64; s; s >>= 1) {
            if (t < s) red[t] = fmaxf(red[t], red[t + s]);
            __syncthreads();
        }
        m = red[0];
        __syncthreads();
        float e[4], ss = 0.f;
        #pragma unroll
        for (int j = 0; j < 4; j++) { e[j] = __expf(v[j] - m); ss += e[j]; }
        red[t] = ss;
        __syncthreads();
        for (int s = 64; s; s >>= 1) {
            if (t < s) red[t] += red[t + s];
            __syncthreads();
        }
        float inv = 1.0f / red[0];
        #pragma unroll
        for (int j = 0; j < 4; j++) g_cdist[b * C + j * 128 + t] = e[j] * inv;
    }
}

// ---------------- K3: cdash partials -----------------------------------------
__global__ void k_cdash_part(const float* __restrict__ cont) {
    int b = blockIdx.x, dch = blockIdx.y, cch = blockIdx.z;
    int d = dch * 128 + threadIdx.x;
    __shared__ float sd[C / NCC];
    if (threadIdx.x < C / NCC)
        sd[threadIdx.x] = g_cdist[b * C + cch * (C / NCC) + threadIdx.x];
    __syncthreads();
    const float* cb = cont + (size_t)(b * C + cch * (C / NCC)) * D + d;
    float a[8] = {0.f, 0.f, 0.f, 0.f, 0.f, 0.f, 0.f, 0.f};
    for (int c0 = 0; c0 < 8; c0++) {
        #pragma unroll
        for (int u = 0; u < 8; u++) {
            int c = u * 8 + c0;
            a[u] = fmaf(sd[c], cb[(size_t)c * D], a[u]);
        }
    }
    float s = ((a[0] + a[1]) + (a[2] + a[3])) + ((a[4] + a[5]) + (a[6] + a[7]));
    g_cdashp[cch][b * D + d] = s;
}

// ---------------- K4: c2q = P @ quesT (bf16+LDSM), colfin in prologue --------
__global__ __launch_bounds__(256) void k_c2q_mma(const float* __restrict__ cont,
                                                 const int*   __restrict__ qmask,
                                                 float* __restrict__ out) {
    const int b  = blockIdx.z;
    const int cm = blockIdx.x * 128;
    extern __shared__ unsigned smemu[];
    unsigned* P  = smemu;                      // 128*68
    unsigned* Bs = smemu + 128 * 68;           // 2*128*68
    float* s_add   = (float*)(Bs + 2 * 128 * 68);
    float* s_max   = s_add + 128;
    float* s_inv   = s_max + 128;
    float* s_cdash = s_inv + 128;              // 768

    const int t = threadIdx.x, lane = t & 31, warp = t >> 5;
    const int g = lane >> 2, tg = lane & 3;
    const int wm = (warp & 3) * 32;
    const int wn = (warp >> 2) * 64;

    // LDSM per-lane offsets (stride 68 words)
    const int rA = (lane & 7) + (lane & 8);
    const int cA = (lane & 16) >> 2;
    const int rB = (lane & 7) + ((lane & 16) >> 1);
    const int cB = (lane & 8) >> 1;
    const unsigned pSh = (unsigned)__cvta_generic_to_shared(P);
    const unsigned bSh = (unsigned)__cvta_generic_to_shared(Bs);
    unsigned offA0 = ((wm + rA) * 68 + cA) * 4;
    unsigned offA1 = offA0 + 16 * 68 * 4;
    unsigned offB[4];
    #pragma unroll
    for (int p = 0; p < 4; p++) offB[p] = ((wn + p * 16 + rB) * 68 + cB) * 4;

    if (t < Q) {
        s_add[t] = (1.0f - (float)qmask[b * Q + t]) * NEG;
        float pm[NCH];
        float m = -INFINITY;
        #pragma unroll
        for (int ch = 0; ch < NCH; ch++) {
            pm[ch] = g_pmax[(b * NCH + ch) * Q + t];
            m = fmaxf(m, pm[ch]);
        }
        float s = 0.f;
        #pragma unroll
        for (int ch = 0; ch < NCH; ch++)
            s += g_psum[(b * NCH + ch) * Q + t] * __expf(pm[ch] - m);
        s_max[t] = m;
        s_inv[t] = 1.0f / s;
    }
    for (int d = t; d < D; d += 256) {
        float s = 0.f;
        #pragma unroll
        for (int u = 0; u < NCC; u++) s += g_cdashp[u][b * D + d];
        s_cdash[d] = s;
    }
    __syncthreads();

    // build P = bf16( exp((sim+add)-max)*inv )
    const int lr = t >> 1;
    const int lk = (t & 1) * 16;
    {
        const float* simrow = g_sim + ((size_t)(b * C + cm + lr)) * Q + lk;
        #pragma unroll
        for (int sc = 0; sc < 4; sc++) {
            #pragma unroll
            for (int j = 0; j < 4; j++) {
                int q0 = sc * 32 + lk + j * 4;
                float4 sv = *(const float4*)(simrow + sc * 32 + j * 4);
                float e0 = __expf((sv.x + s_add[q0+0]) - s_max[q0+0]) * s_inv[q0+0];
                float e1 = __expf((sv.y + s_add[q0+1]) - s_max[q0+1]) * s_inv[q0+1];
                float e2 = __expf((sv.z + s_add[q0+2]) - s_max[q0+2]) * s_inv[q0+2];
                float e3 = __expf((sv.w + s_add[q0+3]) - s_max[q0+3]) * s_inv[q0+3];
                *(uint2*)(P + lr * 68 + (q0 >> 1)) =
                    make_uint2(pack_bf16(e0, e1), pack_bf16(e2, e3));
            }
        }
    }

    const int fr = t >> 1;
    const int fw = (t & 1) * 32;
    const unsigned* qT = g_quesT + (size_t)b * D * 64;

    {
        const unsigned* src = qT + (size_t)fr * 64 + fw;
        unsigned* dst = Bs + fr * 68 + fw;
        #pragma unroll
        for (int j = 0; j < 8; j++) cp16(dst + 4 * j, src + 4 * j);
        cp_commit();
    }

    for (int dn = 0; dn < 6; dn++) {
        const int buf = dn & 1;
        cp_wait0();
        __syncthreads();
        if (dn + 1 < 6) {
            const unsigned* src = qT + (size_t)((dn + 1) * 128 + fr) * 64 + fw;
            unsigned* dst = Bs + (buf ^ 1) * 128 * 68 + fr * 68 + fw;
            #pragma unroll
            for (int j = 0; j < 8; j++) cp16(dst + 4 * j, src + 4 * j);
            cp_commit();
        }

        float acc[2][8][4];
        #pragma unroll
        for (int i = 0; i < 2; i++)
            #pragma unroll
            for (int j = 0; j < 8; j++)
                #pragma unroll
                for (int k = 0; k < 4; k++) acc[i][j][k] = 0.f;

        const unsigned bufOff = (unsigned)buf * 128 * 68 * 4;
        #pragma unroll
        for (int kk = 0; kk < 8; kk++) {
            const unsigned kw = kk * 8 * 4;
            unsigned afr[2][4];
            ldsm4(afr[0], pSh + kw + offA0);
            ldsm4(afr[1], pSh + kw + offA1);
            #pragma unroll
            for (int p = 0; p < 4; p++) {
                unsigned bfr[4];
                ldsm4(bfr, bSh + bufOff + kw + offB[p]);
                mma_bf16(acc[0][2*p],   afr[0], bfr);
                mma_bf16(acc[1][2*p],   afr[1], bfr);
                mma_bf16(acc[0][2*p+1], afr[0], bfr + 2);
                mma_bf16(acc[1][2*p+1], afr[1], bfr + 2);
            }
        }

        #pragma unroll
        for (int mi = 0; mi < 2; mi++) {
            #pragma unroll
            for (int half = 0; half < 2; half++) {
                int cc = cm + wm + mi * 16 + g + half * 8;
                const float* crow = cont + ((size_t)b * C + cc) * D + dn * 128;
                float* obase = out + ((size_t)b * C + cc) * (4 * D);
                #pragma unroll
                for (int ni = 0; ni < 8; ni++) {
                    int col = wn + ni * 8 + 2 * tg;
                    int dg  = dn * 128 + col;
                    float2 cv = *(const float2*)(crow + col);
                    float2 cd = *(const float2*)&s_cdash[dg];
                    float2 v  = make_float2(acc[mi][ni][half * 2 + 0],
                                            acc[mi][ni][half * 2 + 1]);
                    *(float2*)&obase[dg]         = cv;
                    *(float2*)&obase[D + dg]     = v;
                    *(float2*)&obase[2 * D + dg] = make_float2(cv.x * v.x, cv.y * v.y);
                    *(float2*)&obase[3 * D + dg] = make_float2(cv.x * cd.x, cv.y * cd.y);
                }
            }
        }
    }
}

// ---------------- launch -----------------------------------------------------
extern "C" void kernel_launch(void* const* d_in, const int* in_sizes, int n_in,
                              void* d_out, int out_size) {
    const float* cont  = (const float*)d_in[0];
    const int*   cmask = (const int*)d_in[1];
    const float* ques  = (const float*)d_in[2];
    const int*   qmask = (const int*)d_in[3];
    const float* SW    = (const float*)d_in[4];
    float* out = (float*)d_out;

    const int smem_sim = 4 * 128 * 20 * 4 + (256 + 128 + 128) * 4;
    const int smem_c2q = (128 * 68 + 2 * 128 * 68) * 4 + (3 * 128 + 768) * 4;
    cudaFuncSetAttribute(k_sim_mma, cudaFuncAttributeMaxDynamicSharedMemorySize, smem_sim);
    cudaFuncSetAttribute(k_c2q_mma, cudaFuncAttributeMaxDynamicSharedMemorySize, smem_c2q);

    k_trans<<<dim3(B, D / 32), 256>>>(ques);
    k_sim_mma<<<dim3(C / 128, 1, B), 256, smem_sim>>>(cont, ques, SW);
    k_mid<<<dim3(B, NCH + 1), 128>>>(qmask, cmask);
    k_cdash_part<<<dim3(B, 6, NCC), 128>>>(cont);
    k_c2q_mma<<<dim3(C / 128, 1, B), 256, smem_c2q>>>(cont, qmask, out);
}